// round 2
// baseline (speedup 1.0000x reference)
#include <cuda_runtime.h>

// Problem constants
#define Bb 4
#define Ss 2048
#define Ee 1024
#define Hh 16
#define Dd 64
#define SMPAD 68  // 68 floats = 272 B = 17*16 B -> keeps float4 alignment, breaks bank conflicts

// Scratch for projected Q/K/V in (B,H,S,D) layout (allowed: __device__ globals)
__device__ float g_Q[(size_t)Bb * Hh * Ss * Dd];
__device__ float g_K[(size_t)Bb * Hh * Ss * Dd];
__device__ float g_V[(size_t)Bb * Hh * Ss * Dd];

// ---------------------------------------------------------------------------
// Projection GEMM: C[m][n] = sum_e X[m][e] * W[n][e]
// X: (B*S, E) row-major, W: (H*D, E) row-major.
// Output written in (B,H,S,D) layout into g_Q/g_K/g_V selected by `which`.
// Tiles: BM=BN=64, BK=16; 256 threads; 4x4 register micro-tile per thread.
// ---------------------------------------------------------------------------
__global__ __launch_bounds__(256) void proj_kernel(const float* __restrict__ X,
                                                   const float* __restrict__ W,
                                                   int which) {
    __shared__ float AsT[16][SMPAD];  // [kk][m]
    __shared__ float BsT[16][SMPAD];  // [kk][n]
    float* dst = (which == 0) ? g_Q : (which == 1) ? g_K : g_V;

    const int t  = threadIdx.x;
    const int tx = t & 15, ty = t >> 4;
    const int m0 = blockIdx.y * 64;
    const int n0 = blockIdx.x * 64;
    const int lr = t >> 2;        // 0..63 row within tile
    const int lc = (t & 3) * 4;   // 0,4,8,12 within BK=16

    float acc[4][4] = {};
    const float* Xp = X + (size_t)(m0 + lr) * Ee + lc;
    const float* Wp = W + (size_t)(n0 + lr) * Ee + lc;

    for (int k0 = 0; k0 < Ee; k0 += 16) {
        float4 av = *(const float4*)(Xp + k0);
        float4 bv = *(const float4*)(Wp + k0);
        __syncthreads();
        AsT[lc + 0][lr] = av.x; AsT[lc + 1][lr] = av.y;
        AsT[lc + 2][lr] = av.z; AsT[lc + 3][lr] = av.w;
        BsT[lc + 0][lr] = bv.x; BsT[lc + 1][lr] = bv.y;
        BsT[lc + 2][lr] = bv.z; BsT[lc + 3][lr] = bv.w;
        __syncthreads();
#pragma unroll
        for (int kk = 0; kk < 16; kk++) {
            float4 a4 = *(const float4*)&AsT[kk][ty * 4];
            float4 b4 = *(const float4*)&BsT[kk][tx * 4];
            float ar[4] = {a4.x, a4.y, a4.z, a4.w};
            float br[4] = {b4.x, b4.y, b4.z, b4.w};
#pragma unroll
            for (int i = 0; i < 4; i++)
#pragma unroll
                for (int j = 0; j < 4; j++)
                    acc[i][j] += ar[i] * br[j];
        }
    }

    // Write (B,H,S,D): whole block is one batch (S%64==0) and one head (BN==D)
    const int b  = m0 / Ss;
    const int s0 = (m0 % Ss) + ty * 4;
    const int h  = n0 / Dd;
    const int d0 = tx * 4;
#pragma unroll
    for (int i = 0; i < 4; i++) {
        float4 o = {acc[i][0], acc[i][1], acc[i][2], acc[i][3]};
        *(float4*)&dst[(((size_t)b * Hh + h) * Ss + (s0 + i)) * Dd + d0] = o;
    }
}

// ---------------------------------------------------------------------------
// Flash attention (fp32 SIMT). One CTA per (b, h, 64-row q-tile).
// QsT/KsT stored d-major so QK^T inner loop is 2x LDS.128 per 16 FMA.
// Online softmax with 16-lane shuffle reductions; P staged transposed in smem.
// Mask arrives as int32 (harness converts numpy bool -> int32): nonzero = disallowed.
// ---------------------------------------------------------------------------
__global__ __launch_bounds__(256) void attn_kernel(const int* __restrict__ mask,
                                                   float* __restrict__ out) {
    extern __shared__ float sm[];
    float* QsT = sm;                    // [d][row]   64 x SMPAD
    float* KsT = sm + 64 * SMPAD;       // [d][kcol]  64 x SMPAD
    float* Vs  = sm + 2 * 64 * SMPAD;   // [krow][d]  64 x SMPAD
    float* PsT = sm + 3 * 64 * SMPAD;   // [kcol][row] 64 x SMPAD

    const int qt = blockIdx.x, h = blockIdx.y, b = blockIdx.z;
    const int t  = threadIdx.x;
    const int tx = t & 15, ty = t >> 4;
    const int lr = t >> 2;
    const int lc = (t & 3) * 4;

    const float* Qg = g_Q + (((size_t)b * Hh + h) * Ss + qt * 64) * Dd;
    const float* Kg = g_K + (((size_t)b * Hh + h) * Ss) * Dd;
    const float* Vg = g_V + (((size_t)b * Hh + h) * Ss) * Dd;
    const int* mrow = mask + (size_t)b * Ss * Ss + (size_t)(qt * 64) * Ss;

    // Load Q tile, transposed to d-major
#pragma unroll
    for (int i = 0; i < 4; i++) {
        int d0 = lc + i * 16;
        float4 v = *(const float4*)(Qg + lr * Dd + d0);
        QsT[(d0 + 0) * SMPAD + lr] = v.x;
        QsT[(d0 + 1) * SMPAD + lr] = v.y;
        QsT[(d0 + 2) * SMPAD + lr] = v.z;
        QsT[(d0 + 3) * SMPAD + lr] = v.w;
    }

    float acc[4][4] = {};
    float mrun[4], lrun[4];
#pragma unroll
    for (int i = 0; i < 4; i++) { mrun[i] = -1e30f; lrun[i] = 0.f; }

    for (int kt = 0; kt < Ss / 64; kt++) {
        __syncthreads();  // previous iteration's reads of KsT/Vs/PsT complete
        // Load K (transposed) and V tiles
#pragma unroll
        for (int i = 0; i < 4; i++) {
            int d0 = lc + i * 16;
            float4 kv = *(const float4*)(Kg + (size_t)(kt * 64 + lr) * Dd + d0);
            KsT[(d0 + 0) * SMPAD + lr] = kv.x;
            KsT[(d0 + 1) * SMPAD + lr] = kv.y;
            KsT[(d0 + 2) * SMPAD + lr] = kv.z;
            KsT[(d0 + 3) * SMPAD + lr] = kv.w;
            float4 vv = *(const float4*)(Vg + (size_t)(kt * 64 + lr) * Dd + d0);
            *(float4*)&Vs[lr * SMPAD + d0] = vv;
        }
        __syncthreads();

        // S = (Q K^T) for this 64x64 tile; thread owns rows 4ty+, cols 4tx+
        float s[4][4] = {};
#pragma unroll 4
        for (int d = 0; d < 64; d++) {
            float4 q4 = *(const float4*)&QsT[d * SMPAD + 4 * ty];
            float4 k4 = *(const float4*)&KsT[d * SMPAD + 4 * tx];
            float qr[4] = {q4.x, q4.y, q4.z, q4.w};
            float kr[4] = {k4.x, k4.y, k4.z, k4.w};
#pragma unroll
            for (int i = 0; i < 4; i++)
#pragma unroll
                for (int j = 0; j < 4; j++)
                    s[i][j] += qr[i] * kr[j];
        }

        // scale + mask (mask nonzero => disallowed). int32 mask, 16B-aligned int4 loads.
#pragma unroll
        for (int i = 0; i < 4; i++) {
            const int* mp = mrow + (size_t)(4 * ty + i) * Ss + kt * 64 + 4 * tx;
            int4 mv = *(const int4*)mp;
            s[i][0] = mv.x ? -1e30f : s[i][0] * 0.125f;
            s[i][1] = mv.y ? -1e30f : s[i][1] * 0.125f;
            s[i][2] = mv.z ? -1e30f : s[i][2] * 0.125f;
            s[i][3] = mv.w ? -1e30f : s[i][3] * 0.125f;
        }

        // online softmax per row (16 tx lanes hold one row; xor<=8 stays in group)
#pragma unroll
        for (int i = 0; i < 4; i++) {
            float mx = fmaxf(fmaxf(s[i][0], s[i][1]), fmaxf(s[i][2], s[i][3]));
#pragma unroll
            for (int off = 8; off >= 1; off >>= 1)
                mx = fmaxf(mx, __shfl_xor_sync(0xffffffffu, mx, off));
            float mnew = fmaxf(mrun[i], mx);
            float corr = __expf(mrun[i] - mnew);
            mrun[i] = mnew;
            float ls = 0.f;
#pragma unroll
            for (int j = 0; j < 4; j++) {
                s[i][j] = __expf(s[i][j] - mnew);
                ls += s[i][j];
            }
#pragma unroll
            for (int off = 8; off >= 1; off >>= 1)
                ls += __shfl_xor_sync(0xffffffffu, ls, off);
            lrun[i] = lrun[i] * corr + ls;
#pragma unroll
            for (int j = 0; j < 4; j++) acc[i][j] *= corr;
        }

        // stage P transposed: PsT[kcol][row]
#pragma unroll
        for (int j = 0; j < 4; j++) {
            float4 pv = {s[0][j], s[1][j], s[2][j], s[3][j]};
            *(float4*)&PsT[(4 * tx + j) * SMPAD + 4 * ty] = pv;
        }
        __syncthreads();

        // O += P @ V ; thread owns rows 4ty+, d-cols 4tx+
#pragma unroll 4
        for (int kk = 0; kk < 64; kk++) {
            float4 p4 = *(const float4*)&PsT[kk * SMPAD + 4 * ty];
            float4 v4 = *(const float4*)&Vs[kk * SMPAD + 4 * tx];
            float pr[4] = {p4.x, p4.y, p4.z, p4.w};
            float vr[4] = {v4.x, v4.y, v4.z, v4.w};
#pragma unroll
            for (int i = 0; i < 4; i++)
#pragma unroll
                for (int j = 0; j < 4; j++)
                    acc[i][j] += pr[i] * vr[j];
        }
    }

    // epilogue: normalize and write (B, S, H*D)
#pragma unroll
    for (int i = 0; i < 4; i++) {
        float inv = 1.f / fmaxf(lrun[i], 1e-30f);
        float4 o = {acc[i][0] * inv, acc[i][1] * inv, acc[i][2] * inv, acc[i][3] * inv};
        int srow = qt * 64 + 4 * ty + i;
        *(float4*)&out[((size_t)b * Ss + srow) * (Hh * Dd) + h * Dd + 4 * tx] = o;
    }
}

// ---------------------------------------------------------------------------
extern "C" void kernel_launch(void* const* d_in, const int* in_sizes, int n_in,
                              void* d_out, int out_size) {
    const float* q  = (const float*)d_in[0];
    const float* hx = (const float*)d_in[1];
    const int*   mask = (const int*)d_in[2];
    const float* Wq = (const float*)d_in[3];
    const float* Wk = (const float*)d_in[4];
    const float* Wv = (const float*)d_in[5];
    float* out = (float*)d_out;

    dim3 pgrid(Hh * Dd / 64, Bb * Ss / 64);  // (16, 128)
    proj_kernel<<<pgrid, 256>>>(q,  Wq, 0);
    proj_kernel<<<pgrid, 256>>>(hx, Wk, 1);
    proj_kernel<<<pgrid, 256>>>(hx, Wv, 2);

    const int smem = 4 * 64 * SMPAD * (int)sizeof(float);  // 69632 B
    cudaFuncSetAttribute(attn_kernel, cudaFuncAttributeMaxDynamicSharedMemorySize, smem);
    attn_kernel<<<dim3(Ss / 64, Hh, Bb), 256, smem>>>(mask, out);
}

// round 3
// speedup vs baseline: 2.1185x; 2.1185x over previous
#include <cuda_runtime.h>
#include <cstdint>

#define Bb 4
#define Ss 2048
#define Ee 1024
#define Hh 16
#define Dd 64
#define STRD 72   // bf16 smem row stride: 144B -> conflict-free ldmatrix, aligned

// Projected Q/K/V as bf16 hi/lo pairs, stored as packed bf16x2 words.
// Element count per tensor = B*H*S*D = 8388608 -> 4194304 uint32 words.
#define NWORDS (size_t)(Bb * Hh * Ss * Dd / 2)
__device__ uint32_t g_Qh[NWORDS];
__device__ uint32_t g_Ql[NWORDS];
__device__ uint32_t g_Kh[NWORDS];
__device__ uint32_t g_Kl[NWORDS];
__device__ uint32_t g_Vh[NWORDS];
__device__ uint32_t g_Vl[NWORDS];

// ---------------- helpers ----------------
__device__ __forceinline__ uint32_t pack_bf16x2(float lo, float hi) {
    uint32_t u;
    asm("cvt.rn.bf16x2.f32 %0, %1, %2;" : "=r"(u) : "f"(hi), "f"(lo));
    return u;
}
__device__ __forceinline__ float unpack_lo(uint32_t u) { return __uint_as_float(u << 16); }
__device__ __forceinline__ float unpack_hi(uint32_t u) { return __uint_as_float(u & 0xffff0000u); }

__device__ __forceinline__ float ex2f(float x) {
    float r; asm("ex2.approx.f32 %0, %1;" : "=f"(r) : "f"(x)); return r;
}

__device__ __forceinline__ void mma16816(float c[4], const uint32_t a[4], uint32_t b0, uint32_t b1) {
    asm volatile(
        "mma.sync.aligned.m16n8k16.row.col.f32.bf16.bf16.f32 "
        "{%0,%1,%2,%3},{%4,%5,%6,%7},{%8,%9},{%0,%1,%2,%3};\n"
        : "+f"(c[0]), "+f"(c[1]), "+f"(c[2]), "+f"(c[3])
        : "r"(a[0]), "r"(a[1]), "r"(a[2]), "r"(a[3]), "r"(b0), "r"(b1));
}

// A-fragment (m16 x k16) from row-major smem tile T[row][k], stride STRD
__device__ __forceinline__ void ldmA(const unsigned short* t, int row0, int k0, uint32_t r[4]) {
    int lane = threadIdx.x & 31;
    int rr = row0 + (lane & 7) + 8 * ((lane >> 3) & 1);
    int cc = k0 + 8 * (lane >> 4);
    uint32_t a = (uint32_t)__cvta_generic_to_shared(t + rr * STRD + cc);
    asm volatile("ldmatrix.sync.aligned.m8n8.x4.shared.b16 {%0,%1,%2,%3},[%4];"
                 : "=r"(r[0]), "=r"(r[1]), "=r"(r[2]), "=r"(r[3]) : "r"(a));
}
// B-fragments (k16 x n8, two n-tiles n0, n0+8) from row-major tile T[n][k]
__device__ __forceinline__ void ldmB(const unsigned short* t, int n0, int k0, uint32_t r[4]) {
    int lane = threadIdx.x & 31;
    int rr = n0 + (lane & 7) + 8 * (lane >> 4);
    int cc = k0 + 8 * ((lane >> 3) & 1);
    uint32_t a = (uint32_t)__cvta_generic_to_shared(t + rr * STRD + cc);
    asm volatile("ldmatrix.sync.aligned.m8n8.x4.shared.b16 {%0,%1,%2,%3},[%4];"
                 : "=r"(r[0]), "=r"(r[1]), "=r"(r[2]), "=r"(r[3]) : "r"(a));
}
// B-fragments for V (k16 x n8, two n-tiles d0, d0+8) from row-major tile T[kk][d] via .trans
__device__ __forceinline__ void ldmBT(const unsigned short* t, int kk0, int d0, uint32_t r[4]) {
    int lane = threadIdx.x & 31;
    int rr = kk0 + (lane & 7) + 8 * ((lane >> 3) & 1);
    int cc = d0 + 8 * (lane >> 4);
    uint32_t a = (uint32_t)__cvta_generic_to_shared(t + rr * STRD + cc);
    asm volatile("ldmatrix.sync.aligned.m8n8.x4.trans.shared.b16 {%0,%1,%2,%3},[%4];"
                 : "=r"(r[0]), "=r"(r[1]), "=r"(r[2]), "=r"(r[3]) : "r"(a));
}

// ---------------------------------------------------------------------------
// Projections (all three in one kernel, z selects). C = X @ W^T, split-bf16x3.
// BM=128, BN=128, BK=64. 256 threads, warp w owns rows 16w x all 128 cols.
// ---------------------------------------------------------------------------
__global__ __launch_bounds__(256, 2) void proj_kernel(const float* __restrict__ q,
                                                      const float* __restrict__ hx,
                                                      const float* __restrict__ Wq,
                                                      const float* __restrict__ Wk,
                                                      const float* __restrict__ Wv) {
    extern __shared__ unsigned short sm16[];
    unsigned short* Xh = sm16;                 // [128][STRD]
    unsigned short* Xl = Xh + 128 * STRD;
    unsigned short* Wh = Xl + 128 * STRD;
    unsigned short* Wl = Wh + 128 * STRD;

    const int z = blockIdx.z;
    const float* X = (z == 0) ? q : hx;
    const float* W = (z == 0) ? Wq : (z == 1) ? Wk : Wv;
    uint32_t* dsth = (z == 0) ? g_Qh : (z == 1) ? g_Kh : g_Vh;
    uint32_t* dstl = (z == 0) ? g_Ql : (z == 1) ? g_Kl : g_Vl;

    const int tid = threadIdx.x;
    const int wid = tid >> 5, lane = tid & 31;
    const int g = lane >> 2, t4 = lane & 3;
    const int mblk = blockIdx.y, nblk = blockIdx.x;

    float c[16][4] = {};

    for (int e0 = 0; e0 < Ee; e0 += 64) {
        __syncthreads();
        // load + split X tile (128x64 f32) and W tile (128x64 f32)
#pragma unroll
        for (int i = 0; i < 8; i++) {
            int slot = i * 256 + tid;          // 2048 float4 slots
            int r = slot >> 4, c4 = (slot & 15) * 4;
            float4 v = *(const float4*)(X + (size_t)(mblk * 128 + r) * Ee + e0 + c4);
            uint32_t h0 = pack_bf16x2(v.x, v.y);
            uint32_t h1 = pack_bf16x2(v.z, v.w);
            uint32_t l0 = pack_bf16x2(v.x - unpack_lo(h0), v.y - unpack_hi(h0));
            uint32_t l1 = pack_bf16x2(v.z - unpack_lo(h1), v.w - unpack_hi(h1));
            *(uint2*)(Xh + r * STRD + c4) = make_uint2(h0, h1);
            *(uint2*)(Xl + r * STRD + c4) = make_uint2(l0, l1);
            float4 w = *(const float4*)(W + (size_t)(nblk * 128 + r) * Ee + e0 + c4);
            uint32_t wh0 = pack_bf16x2(w.x, w.y);
            uint32_t wh1 = pack_bf16x2(w.z, w.w);
            uint32_t wl0 = pack_bf16x2(w.x - unpack_lo(wh0), w.y - unpack_hi(wh0));
            uint32_t wl1 = pack_bf16x2(w.z - unpack_lo(wh1), w.w - unpack_hi(wh1));
            *(uint2*)(Wh + r * STRD + c4) = make_uint2(wh0, wh1);
            *(uint2*)(Wl + r * STRD + c4) = make_uint2(wl0, wl1);
        }
        __syncthreads();

#pragma unroll
        for (int ks = 0; ks < 4; ks++) {
            uint32_t axh[4], axl[4];
            ldmA(Xh, wid * 16, ks * 16, axh);
            ldmA(Xl, wid * 16, ks * 16, axl);
#pragma unroll
            for (int nt2 = 0; nt2 < 8; nt2++) {
                uint32_t bh[4], bl[4];
                ldmB(Wh, nt2 * 16, ks * 16, bh);
                ldmB(Wl, nt2 * 16, ks * 16, bl);
                mma16816(c[2 * nt2],     axh, bh[0], bh[1]);
                mma16816(c[2 * nt2],     axh, bl[0], bl[1]);
                mma16816(c[2 * nt2],     axl, bh[0], bh[1]);
                mma16816(c[2 * nt2 + 1], axh, bh[2], bh[3]);
                mma16816(c[2 * nt2 + 1], axh, bl[2], bl[3]);
                mma16816(c[2 * nt2 + 1], axl, bh[2], bh[3]);
            }
        }
    }

    // epilogue: split accum to hi/lo bf16 pairs, write (B,H,S,D)
    const int m0 = mblk * 128 + wid * 16 + g;
    const int b = m0 >> 11, s0 = m0 & 2047;
#pragma unroll
    for (int nt = 0; nt < 16; nt++) {
        int n = nblk * 128 + nt * 8 + 2 * t4;
        int hh = n >> 6, d = n & 63;
        // row m0
        {
            uint32_t uh = pack_bf16x2(c[nt][0], c[nt][1]);
            uint32_t ul = pack_bf16x2(c[nt][0] - unpack_lo(uh), c[nt][1] - unpack_hi(uh));
            size_t w = ((((size_t)b * Hh + hh) * Ss + s0) * Dd + d) >> 1;
            dsth[w] = uh; dstl[w] = ul;
        }
        // row m0+8
        {
            uint32_t uh = pack_bf16x2(c[nt][2], c[nt][3]);
            uint32_t ul = pack_bf16x2(c[nt][2] - unpack_lo(uh), c[nt][3] - unpack_hi(uh));
            size_t w = ((((size_t)b * Hh + hh) * Ss + (s0 + 8)) * Dd + d) >> 1;
            dsth[w] = uh; dstl[w] = ul;
        }
    }
}

// ---------------------------------------------------------------------------
// Flash attention, bf16x3 tensor cores. CTA = (qt: 128 rows, h, b).
// Warp w owns q-rows [16w,16w+16) x all 128 k-cols -> warp-local softmax.
// ---------------------------------------------------------------------------
#define SCLOG2 0.18033688011112042f  // 0.125 * log2(e)
#define NEGBIG -1e30f

__global__ __launch_bounds__(256, 1) void attn_kernel(const int* __restrict__ mask,
                                                      float* __restrict__ out) {
    extern __shared__ unsigned short sm16[];
    unsigned short* Qh = sm16;                 // 6 tiles of [128][STRD]
    unsigned short* Ql = Qh + 128 * STRD;
    unsigned short* Kh = Ql + 128 * STRD;
    unsigned short* Kl = Kh + 128 * STRD;
    unsigned short* Vh = Kl + 128 * STRD;
    unsigned short* Vl = Vh + 128 * STRD;

    const int qt = blockIdx.x, h = blockIdx.y, b = blockIdx.z;
    const int tid = threadIdx.x;
    const int wid = tid >> 5, lane = tid & 31;
    const int g = lane >> 2, t4 = lane & 3;

    const size_t bh_base = ((size_t)b * Hh + h) * Ss;   // row base in (B*H*S)
    const size_t qw = (bh_base + qt * 128) * Dd / 2;    // word index of Q tile

    // load Q hi/lo tiles (128x64 bf16 each = 1024 int4 per tile)
#pragma unroll
    for (int i = 0; i < 4; i++) {
        int slot = i * 256 + tid;
        int r = slot >> 3, c16 = slot & 7;               // 8 int4 per row
        *(int4*)(Qh + r * STRD + c16 * 8) = *(const int4*)&g_Qh[qw + r * 32 + c16 * 4];
        *(int4*)(Ql + r * STRD + c16 * 8) = *(const int4*)&g_Ql[qw + r * 32 + c16 * 4];
    }

    float o[8][4] = {};
    float mrun0 = NEGBIG, mrun1 = NEGBIG, lrun0 = 0.f, lrun1 = 0.f;

    const int r0 = qt * 128 + wid * 16 + g;
    const int r1 = r0 + 8;
    const int* mp0 = mask + ((size_t)b * Ss + r0) * Ss;
    const int* mp1 = mask + ((size_t)b * Ss + r1) * Ss;

    for (int kt = 0; kt < Ss / 128; kt++) {
        __syncthreads();
        const size_t kw = (bh_base + kt * 128) * Dd / 2;
#pragma unroll
        for (int i = 0; i < 4; i++) {
            int slot = i * 256 + tid;
            int r = slot >> 3, c16 = slot & 7;
            size_t srcw = kw + r * 32 + c16 * 4;
            int smo = r * STRD + c16 * 8;
            *(int4*)(Kh + smo) = *(const int4*)&g_Kh[srcw];
            *(int4*)(Kl + smo) = *(const int4*)&g_Kl[srcw];
            *(int4*)(Vh + smo) = *(const int4*)&g_Vh[srcw];
            *(int4*)(Vl + smo) = *(const int4*)&g_Vl[srcw];
        }
        __syncthreads();

        // ---- S = Q K^T (16 x 128 per warp), bf16x3 ----
        float s[16][4] = {};
#pragma unroll
        for (int ks = 0; ks < 4; ks++) {
            uint32_t aqh[4], aql[4];
            ldmA(Qh, wid * 16, ks * 16, aqh);
            ldmA(Ql, wid * 16, ks * 16, aql);
#pragma unroll
            for (int nt2 = 0; nt2 < 8; nt2++) {
                uint32_t bh2[4], bl2[4];
                ldmB(Kh, nt2 * 16, ks * 16, bh2);
                ldmB(Kl, nt2 * 16, ks * 16, bl2);
                mma16816(s[2 * nt2],     aqh, bh2[0], bh2[1]);
                mma16816(s[2 * nt2],     aqh, bl2[0], bl2[1]);
                mma16816(s[2 * nt2],     aql, bh2[0], bh2[1]);
                mma16816(s[2 * nt2 + 1], aqh, bh2[2], bh2[3]);
                mma16816(s[2 * nt2 + 1], aqh, bl2[2], bl2[3]);
                mma16816(s[2 * nt2 + 1], aql, bh2[2], bh2[3]);
            }
        }

        // ---- mask + scale into log2 domain ----
        const int cb = kt * 128 + 2 * t4;
#pragma unroll
        for (int nt = 0; nt < 16; nt++) {
            int2 m0 = *(const int2*)(mp0 + cb + nt * 8);
            int2 m1 = *(const int2*)(mp1 + cb + nt * 8);
            s[nt][0] = m0.x ? NEGBIG : s[nt][0] * SCLOG2;
            s[nt][1] = m0.y ? NEGBIG : s[nt][1] * SCLOG2;
            s[nt][2] = m1.x ? NEGBIG : s[nt][2] * SCLOG2;
            s[nt][3] = m1.y ? NEGBIG : s[nt][3] * SCLOG2;
        }

        // ---- online softmax (warp-local; rows owned by lane quads) ----
        float mx0 = NEGBIG, mx1 = NEGBIG;
#pragma unroll
        for (int nt = 0; nt < 16; nt++) {
            mx0 = fmaxf(mx0, fmaxf(s[nt][0], s[nt][1]));
            mx1 = fmaxf(mx1, fmaxf(s[nt][2], s[nt][3]));
        }
        mx0 = fmaxf(mx0, __shfl_xor_sync(0xffffffffu, mx0, 1));
        mx0 = fmaxf(mx0, __shfl_xor_sync(0xffffffffu, mx0, 2));
        mx1 = fmaxf(mx1, __shfl_xor_sync(0xffffffffu, mx1, 1));
        mx1 = fmaxf(mx1, __shfl_xor_sync(0xffffffffu, mx1, 2));
        float mnew0 = fmaxf(mrun0, mx0), mnew1 = fmaxf(mrun1, mx1);
        float corr0 = ex2f(mrun0 - mnew0), corr1 = ex2f(mrun1 - mnew1);
        mrun0 = mnew0; mrun1 = mnew1;

        float ls0 = 0.f, ls1 = 0.f;
#pragma unroll
        for (int nt = 0; nt < 16; nt++) {
            s[nt][0] = ex2f(s[nt][0] - mnew0);
            s[nt][1] = ex2f(s[nt][1] - mnew0);
            s[nt][2] = ex2f(s[nt][2] - mnew1);
            s[nt][3] = ex2f(s[nt][3] - mnew1);
            ls0 += s[nt][0] + s[nt][1];
            ls1 += s[nt][2] + s[nt][3];
        }
        ls0 += __shfl_xor_sync(0xffffffffu, ls0, 1);
        ls0 += __shfl_xor_sync(0xffffffffu, ls0, 2);
        ls1 += __shfl_xor_sync(0xffffffffu, ls1, 1);
        ls1 += __shfl_xor_sync(0xffffffffu, ls1, 2);
        lrun0 = lrun0 * corr0 + ls0;
        lrun1 = lrun1 * corr1 + ls1;
#pragma unroll
        for (int nd = 0; nd < 8; nd++) {
            o[nd][0] *= corr0; o[nd][1] *= corr0;
            o[nd][2] *= corr1; o[nd][3] *= corr1;
        }

        // ---- P -> bf16 hi/lo A-fragments (in-register) ----
        uint32_t ph[32], pl[32];
#pragma unroll
        for (int nt = 0; nt < 16; nt++) {
            uint32_t u0 = pack_bf16x2(s[nt][0], s[nt][1]);
            pl[2 * nt] = pack_bf16x2(s[nt][0] - unpack_lo(u0), s[nt][1] - unpack_hi(u0));
            ph[2 * nt] = u0;
            uint32_t u1 = pack_bf16x2(s[nt][2], s[nt][3]);
            pl[2 * nt + 1] = pack_bf16x2(s[nt][2] - unpack_lo(u1), s[nt][3] - unpack_hi(u1));
            ph[2 * nt + 1] = u1;
        }

        // ---- O += P V, bf16x3 ----
#pragma unroll
        for (int ks2 = 0; ks2 < 8; ks2++) {
            const uint32_t pah[4] = {ph[4 * ks2], ph[4 * ks2 + 1], ph[4 * ks2 + 2], ph[4 * ks2 + 3]};
            const uint32_t pal[4] = {pl[4 * ks2], pl[4 * ks2 + 1], pl[4 * ks2 + 2], pl[4 * ks2 + 3]};
#pragma unroll
            for (int d2 = 0; d2 < 4; d2++) {
                uint32_t bvh[4], bvl[4];
                ldmBT(Vh, ks2 * 16, d2 * 16, bvh);
                ldmBT(Vl, ks2 * 16, d2 * 16, bvl);
                mma16816(o[2 * d2],     pah, bvh[0], bvh[1]);
                mma16816(o[2 * d2],     pah, bvl[0], bvl[1]);
                mma16816(o[2 * d2],     pal, bvh[0], bvh[1]);
                mma16816(o[2 * d2 + 1], pah, bvh[2], bvh[3]);
                mma16816(o[2 * d2 + 1], pah, bvl[2], bvl[3]);
                mma16816(o[2 * d2 + 1], pal, bvh[2], bvh[3]);
            }
        }
    }

    // ---- epilogue: normalize, write (B, S, H*D) fp32 ----
    float inv0 = 1.f / fmaxf(lrun0, 1e-30f);
    float inv1 = 1.f / fmaxf(lrun1, 1e-30f);
#pragma unroll
    for (int nd = 0; nd < 8; nd++) {
        int d = nd * 8 + 2 * t4;
        *(float2*)&out[((size_t)b * Ss + r0) * (Hh * Dd) + h * Dd + d] =
            make_float2(o[nd][0] * inv0, o[nd][1] * inv0);
        *(float2*)&out[((size_t)b * Ss + r1) * (Hh * Dd) + h * Dd + d] =
            make_float2(o[nd][2] * inv1, o[nd][3] * inv1);
    }
}

// ---------------------------------------------------------------------------
extern "C" void kernel_launch(void* const* d_in, const int* in_sizes, int n_in,
                              void* d_out, int out_size) {
    const float* q  = (const float*)d_in[0];
    const float* hx = (const float*)d_in[1];
    const int* mask = (const int*)d_in[2];
    const float* Wq = (const float*)d_in[3];
    const float* Wk = (const float*)d_in[4];
    const float* Wv = (const float*)d_in[5];
    float* out = (float*)d_out;

    const int psmem = 4 * 128 * STRD * 2;   // 73728 B
    cudaFuncSetAttribute(proj_kernel, cudaFuncAttributeMaxDynamicSharedMemorySize, psmem);
    proj_kernel<<<dim3(Hh * Dd / 128, Bb * Ss / 128, 3), 256, psmem>>>(q, hx, Wq, Wk, Wv);

    const int asmem = 6 * 128 * STRD * 2;   // 110592 B
    cudaFuncSetAttribute(attn_kernel, cudaFuncAttributeMaxDynamicSharedMemorySize, asmem);
    attn_kernel<<<dim3(Ss / 128, Hh, Bb), 256, asmem>>>(mask, out);
}

// round 4
// speedup vs baseline: 4.2358x; 1.9994x over previous
#include <cuda_runtime.h>
#include <cuda_fp16.h>
#include <cstdint>

#define Bb 4
#define Ss 2048
#define Ee 1024
#define Hh 16
#define Dd 64
#define STRD 72   // fp16 smem row stride: 144B = 9*16B -> conflict-free ldmatrix phases

// Projected tensors as packed fp16x2 words. Q: hi+lo (exact side of QK^T);
// K, V: single fp16 (rounded side; error budget per validated model).
#define NWORDS (size_t)(Bb * Hh * Ss * Dd / 2)
__device__ uint32_t g_Qh[NWORDS];
__device__ uint32_t g_Ql[NWORDS];
__device__ uint32_t g_Kh[NWORDS];
__device__ uint32_t g_Vh[NWORDS];

// ---------------- helpers ----------------
__device__ __forceinline__ uint32_t pack_f16x2(float lo, float hi) {
    __half2 h = __floats2half2_rn(lo, hi);   // lo -> low half
    return *(uint32_t*)&h;
}
__device__ __forceinline__ float2 unpack_f16x2(uint32_t u) {
    __half2 h = *(__half2*)&u;
    return __half22float2(h);
}
__device__ __forceinline__ float ex2f(float x) {
    float r; asm("ex2.approx.f32 %0, %1;" : "=f"(r) : "f"(x)); return r;
}
__device__ __forceinline__ void mma16816(float c[4], const uint32_t a[4], uint32_t b0, uint32_t b1) {
    asm volatile(
        "mma.sync.aligned.m16n8k16.row.col.f32.f16.f16.f32 "
        "{%0,%1,%2,%3},{%4,%5,%6,%7},{%8,%9},{%0,%1,%2,%3};\n"
        : "+f"(c[0]), "+f"(c[1]), "+f"(c[2]), "+f"(c[3])
        : "r"(a[0]), "r"(a[1]), "r"(a[2]), "r"(a[3]), "r"(b0), "r"(b1));
}
// A-fragment (m16 x k16) from row-major tile T[row][k], stride STRD
__device__ __forceinline__ void ldmA(const unsigned short* t, int row0, int k0, uint32_t r[4]) {
    int lane = threadIdx.x & 31;
    int rr = row0 + (lane & 7) + 8 * ((lane >> 3) & 1);
    int cc = k0 + 8 * (lane >> 4);
    uint32_t a = (uint32_t)__cvta_generic_to_shared(t + rr * STRD + cc);
    asm volatile("ldmatrix.sync.aligned.m8n8.x4.shared.b16 {%0,%1,%2,%3},[%4];"
                 : "=r"(r[0]), "=r"(r[1]), "=r"(r[2]), "=r"(r[3]) : "r"(a));
}
// B-fragments (k16 x n8, n-tiles n0, n0+8) from row-major tile T[n][k]
__device__ __forceinline__ void ldmB(const unsigned short* t, int n0, int k0, uint32_t r[4]) {
    int lane = threadIdx.x & 31;
    int rr = n0 + (lane & 7) + 8 * (lane >> 4);
    int cc = k0 + 8 * ((lane >> 3) & 1);
    uint32_t a = (uint32_t)__cvta_generic_to_shared(t + rr * STRD + cc);
    asm volatile("ldmatrix.sync.aligned.m8n8.x4.shared.b16 {%0,%1,%2,%3},[%4];"
                 : "=r"(r[0]), "=r"(r[1]), "=r"(r[2]), "=r"(r[3]) : "r"(a));
}
// B-fragments for V (k16 x n8, d-tiles d0, d0+8) from row-major tile T[kk][d] via .trans
__device__ __forceinline__ void ldmBT(const unsigned short* t, int kk0, int d0, uint32_t r[4]) {
    int lane = threadIdx.x & 31;
    int rr = kk0 + (lane & 7) + 8 * ((lane >> 3) & 1);
    int cc = d0 + 8 * (lane >> 4);
    uint32_t a = (uint32_t)__cvta_generic_to_shared(t + rr * STRD + cc);
    asm volatile("ldmatrix.sync.aligned.m8n8.x4.trans.shared.b16 {%0,%1,%2,%3},[%4];"
                 : "=r"(r[0]), "=r"(r[1]), "=r"(r[2]), "=r"(r[3]) : "r"(a));
}
__device__ __forceinline__ void cp16(unsigned short* smem_dst, const void* gsrc) {
    uint32_t s = (uint32_t)__cvta_generic_to_shared(smem_dst);
    asm volatile("cp.async.ca.shared.global [%0], [%1], 16;" :: "r"(s), "l"(gsrc));
}

// ---------------------------------------------------------------------------
// Projections: C = X @ W^T, 2-term fp16 split: Xh*(Wh+Wl).
// BM=BN=128, BK=64, 256 threads, warp owns 16 rows x 128 cols.
// z=0 -> Q (store hi+lo), z=1 -> K (single), z=2 -> V (single).
// ---------------------------------------------------------------------------
__global__ __launch_bounds__(256, 2) void proj_kernel(const float* __restrict__ q,
                                                      const float* __restrict__ hx,
                                                      const float* __restrict__ Wq,
                                                      const float* __restrict__ Wk,
                                                      const float* __restrict__ Wv) {
    extern __shared__ unsigned short sm16[];
    unsigned short* Xh = sm16;                 // [128][STRD]
    unsigned short* Wh = Xh + 128 * STRD;
    unsigned short* Wl = Wh + 128 * STRD;

    const int z = blockIdx.z;
    const float* X = (z == 0) ? q : hx;
    const float* W = (z == 0) ? Wq : (z == 1) ? Wk : Wv;
    uint32_t* dsth = (z == 0) ? g_Qh : (z == 1) ? g_Kh : g_Vh;

    const int tid = threadIdx.x;
    const int wid = tid >> 5, lane = tid & 31;
    const int g = lane >> 2, t4 = lane & 3;
    const int mblk = blockIdx.y, nblk = blockIdx.x;

    float c[16][4] = {};

    for (int e0 = 0; e0 < Ee; e0 += 64) {
        __syncthreads();
#pragma unroll
        for (int i = 0; i < 8; i++) {
            int slot = i * 256 + tid;          // 2048 float4 slots
            int r = slot >> 4, c4 = (slot & 15) * 4;
            float4 v = *(const float4*)(X + (size_t)(mblk * 128 + r) * Ee + e0 + c4);
            *(uint2*)(Xh + r * STRD + c4) =
                make_uint2(pack_f16x2(v.x, v.y), pack_f16x2(v.z, v.w));
            float4 w = *(const float4*)(W + (size_t)(nblk * 128 + r) * Ee + e0 + c4);
            uint32_t wh0 = pack_f16x2(w.x, w.y);
            uint32_t wh1 = pack_f16x2(w.z, w.w);
            float2 f0 = unpack_f16x2(wh0), f1 = unpack_f16x2(wh1);
            *(uint2*)(Wh + r * STRD + c4) = make_uint2(wh0, wh1);
            *(uint2*)(Wl + r * STRD + c4) =
                make_uint2(pack_f16x2(w.x - f0.x, w.y - f0.y),
                           pack_f16x2(w.z - f1.x, w.w - f1.y));
        }
        __syncthreads();

#pragma unroll
        for (int ks = 0; ks < 4; ks++) {
            uint32_t ax[4];
            ldmA(Xh, wid * 16, ks * 16, ax);
#pragma unroll
            for (int nt2 = 0; nt2 < 8; nt2++) {
                uint32_t bh[4], bl[4];
                ldmB(Wh, nt2 * 16, ks * 16, bh);
                ldmB(Wl, nt2 * 16, ks * 16, bl);
                mma16816(c[2 * nt2],     ax, bh[0], bh[1]);
                mma16816(c[2 * nt2],     ax, bl[0], bl[1]);
                mma16816(c[2 * nt2 + 1], ax, bh[2], bh[3]);
                mma16816(c[2 * nt2 + 1], ax, bl[2], bl[3]);
            }
        }
    }

    // epilogue -> (B,H,S,D) packed fp16x2 words
    const int m0 = mblk * 128 + wid * 16 + g;
    const int b = m0 >> 11, s0 = m0 & 2047;
#pragma unroll
    for (int nt = 0; nt < 16; nt++) {
        int n = nblk * 128 + nt * 8 + 2 * t4;
        int hh = n >> 6, d = n & 63;
        size_t w0 = ((((size_t)b * Hh + hh) * Ss + s0) * Dd + d) >> 1;
        size_t w1 = ((((size_t)b * Hh + hh) * Ss + (s0 + 8)) * Dd + d) >> 1;
        uint32_t uh0 = pack_f16x2(c[nt][0], c[nt][1]);
        uint32_t uh1 = pack_f16x2(c[nt][2], c[nt][3]);
        dsth[w0] = uh0;
        dsth[w1] = uh1;
        if (z == 0) {
            float2 f0 = unpack_f16x2(uh0), f1 = unpack_f16x2(uh1);
            g_Ql[w0] = pack_f16x2(c[nt][0] - f0.x, c[nt][1] - f0.y);
            g_Ql[w1] = pack_f16x2(c[nt][2] - f1.x, c[nt][3] - f1.y);
        }
    }
}

// ---------------------------------------------------------------------------
// Flash attention, fp16 tensor cores, 2-term splits, cp.async double-buffered
// K/V. CTA = (qt: 128 q-rows, h, b); warp owns 16 q-rows -> warp-local softmax.
// ---------------------------------------------------------------------------
#define SCLOG2 0.18033688011112042f  // 0.125 * log2(e)
#define NEGBIG -1e30f
#define NKT (Ss / 128)

__global__ __launch_bounds__(256, 1) void attn_kernel(const int* __restrict__ mask,
                                                      float* __restrict__ out) {
    extern __shared__ unsigned short sm16[];
    unsigned short* Qh = sm16;                 // tiles of [128][STRD]
    unsigned short* Ql = Qh + 128 * STRD;
    unsigned short* Kb[2] = {Ql + 128 * STRD, Ql + 3 * 128 * STRD};
    unsigned short* Vb[2] = {Ql + 2 * 128 * STRD, Ql + 4 * 128 * STRD};

    const int qt = blockIdx.x, h = blockIdx.y, b = blockIdx.z;
    const int tid = threadIdx.x;
    const int wid = tid >> 5, lane = tid & 31;
    const int g = lane >> 2, t4 = lane & 3;

    const size_t bh_base = ((size_t)b * Hh + h) * Ss;
    const size_t qw = (bh_base + qt * 128) * (Dd / 2);
    const uint32_t* Kg = g_Kh + bh_base * (Dd / 2);
    const uint32_t* Vg = g_Vh + bh_base * (Dd / 2);

    // Q hi/lo tiles (plain loads; once per CTA)
#pragma unroll
    for (int i = 0; i < 4; i++) {
        int slot = i * 256 + tid;
        int r = slot >> 3, c = slot & 7;
        *(int4*)(Qh + r * STRD + c * 8) = *(const int4*)&g_Qh[qw + r * 32 + c * 4];
        *(int4*)(Ql + r * STRD + c * 8) = *(const int4*)&g_Ql[qw + r * 32 + c * 4];
    }

    // async K/V tile issue: 128 rows x 8 chunks of 16B per tensor
#define ISSUE_KV(kt, buf)                                                       \
    {                                                                           \
        const uint32_t* ks_ = Kg + (size_t)(kt) * 128 * 32;                     \
        const uint32_t* vs_ = Vg + (size_t)(kt) * 128 * 32;                     \
        _Pragma("unroll")                                                       \
        for (int i_ = 0; i_ < 4; i_++) {                                        \
            int slot_ = i_ * 256 + tid;                                         \
            int r_ = slot_ >> 3, c_ = slot_ & 7;                                \
            cp16(Kb[buf] + r_ * STRD + c_ * 8, ks_ + r_ * 32 + c_ * 4);         \
            cp16(Vb[buf] + r_ * STRD + c_ * 8, vs_ + r_ * 32 + c_ * 4);         \
        }                                                                       \
        asm volatile("cp.async.commit_group;");                                 \
    }

    ISSUE_KV(0, 0);

    float o[8][4] = {};
    float mrun0 = NEGBIG, mrun1 = NEGBIG, lrun0 = 0.f, lrun1 = 0.f;

    const int r0 = qt * 128 + wid * 16 + g;
    const int r1 = r0 + 8;
    const int* mp0 = mask + ((size_t)b * Ss + r0) * Ss;
    const int* mp1 = mask + ((size_t)b * Ss + r1) * Ss;

    for (int kt = 0; kt < NKT; kt++) {
        if (kt + 1 < NKT) {
            ISSUE_KV(kt + 1, (kt + 1) & 1);
            asm volatile("cp.async.wait_group 1;");
        } else {
            asm volatile("cp.async.wait_group 0;");
        }
        __syncthreads();
        const unsigned short* Kt = Kb[kt & 1];
        const unsigned short* Vt = Vb[kt & 1];

        // ---- S = (Qh+Ql) Kh^T : 16 x 128 per warp ----
        float s[16][4] = {};
#pragma unroll
        for (int ks = 0; ks < 4; ks++) {
            uint32_t aqh[4], aql[4];
            ldmA(Qh, wid * 16, ks * 16, aqh);
            ldmA(Ql, wid * 16, ks * 16, aql);
#pragma unroll
            for (int nt2 = 0; nt2 < 8; nt2++) {
                uint32_t bk[4];
                ldmB(Kt, nt2 * 16, ks * 16, bk);
                mma16816(s[2 * nt2],     aqh, bk[0], bk[1]);
                mma16816(s[2 * nt2],     aql, bk[0], bk[1]);
                mma16816(s[2 * nt2 + 1], aqh, bk[2], bk[3]);
                mma16816(s[2 * nt2 + 1], aql, bk[2], bk[3]);
            }
        }

        // ---- mask + scale into log2 domain ----
        const int cb = kt * 128 + 2 * t4;
#pragma unroll
        for (int nt = 0; nt < 16; nt++) {
            int2 m0 = *(const int2*)(mp0 + cb + nt * 8);
            int2 m1 = *(const int2*)(mp1 + cb + nt * 8);
            s[nt][0] = m0.x ? NEGBIG : s[nt][0] * SCLOG2;
            s[nt][1] = m0.y ? NEGBIG : s[nt][1] * SCLOG2;
            s[nt][2] = m1.x ? NEGBIG : s[nt][2] * SCLOG2;
            s[nt][3] = m1.y ? NEGBIG : s[nt][3] * SCLOG2;
        }

        // ---- online softmax (warp-local) ----
        float mx0 = NEGBIG, mx1 = NEGBIG;
#pragma unroll
        for (int nt = 0; nt < 16; nt++) {
            mx0 = fmaxf(mx0, fmaxf(s[nt][0], s[nt][1]));
            mx1 = fmaxf(mx1, fmaxf(s[nt][2], s[nt][3]));
        }
        mx0 = fmaxf(mx0, __shfl_xor_sync(0xffffffffu, mx0, 1));
        mx0 = fmaxf(mx0, __shfl_xor_sync(0xffffffffu, mx0, 2));
        mx1 = fmaxf(mx1, __shfl_xor_sync(0xffffffffu, mx1, 1));
        mx1 = fmaxf(mx1, __shfl_xor_sync(0xffffffffu, mx1, 2));
        float mnew0 = fmaxf(mrun0, mx0), mnew1 = fmaxf(mrun1, mx1);
        float corr0 = ex2f(mrun0 - mnew0), corr1 = ex2f(mrun1 - mnew1);
        mrun0 = mnew0; mrun1 = mnew1;

        float ls0 = 0.f, ls1 = 0.f;
#pragma unroll
        for (int nt = 0; nt < 16; nt++) {
            s[nt][0] = ex2f(s[nt][0] - mnew0);
            s[nt][1] = ex2f(s[nt][1] - mnew0);
            s[nt][2] = ex2f(s[nt][2] - mnew1);
            s[nt][3] = ex2f(s[nt][3] - mnew1);
            ls0 += s[nt][0] + s[nt][1];
            ls1 += s[nt][2] + s[nt][3];
        }
        ls0 += __shfl_xor_sync(0xffffffffu, ls0, 1);
        ls0 += __shfl_xor_sync(0xffffffffu, ls0, 2);
        ls1 += __shfl_xor_sync(0xffffffffu, ls1, 1);
        ls1 += __shfl_xor_sync(0xffffffffu, ls1, 2);
        lrun0 = lrun0 * corr0 + ls0;
        lrun1 = lrun1 * corr1 + ls1;
#pragma unroll
        for (int nd = 0; nd < 8; nd++) {
            o[nd][0] *= corr0; o[nd][1] *= corr0;
            o[nd][2] *= corr1; o[nd][3] *= corr1;
        }

        // ---- P -> fp16 hi/lo A-fragments (in-register, exact side) ----
        uint32_t ph[32], pl[32];
#pragma unroll
        for (int nt = 0; nt < 16; nt++) {
            uint32_t u0 = pack_f16x2(s[nt][0], s[nt][1]);
            float2 f0 = unpack_f16x2(u0);
            ph[2 * nt] = u0;
            pl[2 * nt] = pack_f16x2(s[nt][0] - f0.x, s[nt][1] - f0.y);
            uint32_t u1 = pack_f16x2(s[nt][2], s[nt][3]);
            float2 f1 = unpack_f16x2(u1);
            ph[2 * nt + 1] = u1;
            pl[2 * nt + 1] = pack_f16x2(s[nt][2] - f1.x, s[nt][3] - f1.y);
        }

        // ---- O += (Ph+Pl) Vh ----
#pragma unroll
        for (int ks2 = 0; ks2 < 8; ks2++) {
            const uint32_t pah[4] = {ph[4 * ks2], ph[4 * ks2 + 1], ph[4 * ks2 + 2], ph[4 * ks2 + 3]};
            const uint32_t pal[4] = {pl[4 * ks2], pl[4 * ks2 + 1], pl[4 * ks2 + 2], pl[4 * ks2 + 3]};
#pragma unroll
            for (int d2 = 0; d2 < 4; d2++) {
                uint32_t bv[4];
                ldmBT(Vt, ks2 * 16, d2 * 16, bv);
                mma16816(o[2 * d2],     pah, bv[0], bv[1]);
                mma16816(o[2 * d2],     pal, bv[0], bv[1]);
                mma16816(o[2 * d2 + 1], pah, bv[2], bv[3]);
                mma16816(o[2 * d2 + 1], pal, bv[2], bv[3]);
            }
        }
        __syncthreads();  // all warps done with buf (kt&1) before next issue overwrites it
    }

    // ---- epilogue: normalize, write (B, S, H*D) fp32 ----
    float inv0 = 1.f / fmaxf(lrun0, 1e-30f);
    float inv1 = 1.f / fmaxf(lrun1, 1e-30f);
#pragma unroll
    for (int nd = 0; nd < 8; nd++) {
        int d = nd * 8 + 2 * t4;
        *(float2*)&out[((size_t)b * Ss + r0) * (Hh * Dd) + h * Dd + d] =
            make_float2(o[nd][0] * inv0, o[nd][1] * inv0);
        *(float2*)&out[((size_t)b * Ss + r1) * (Hh * Dd) + h * Dd + d] =
            make_float2(o[nd][2] * inv1, o[nd][3] * inv1);
    }
}

// ---------------------------------------------------------------------------
extern "C" void kernel_launch(void* const* d_in, const int* in_sizes, int n_in,
                              void* d_out, int out_size) {
    const float* q  = (const float*)d_in[0];
    const float* hx = (const float*)d_in[1];
    const int* mask = (const int*)d_in[2];
    const float* Wq = (const float*)d_in[3];
    const float* Wk = (const float*)d_in[4];
    const float* Wv = (const float*)d_in[5];
    float* out = (float*)d_out;

    const int psmem = 3 * 128 * STRD * 2;   // 55296 B
    cudaFuncSetAttribute(proj_kernel, cudaFuncAttributeMaxDynamicSharedMemorySize, psmem);
    proj_kernel<<<dim3(Hh * Dd / 128, Bb * Ss / 128, 3), 256, psmem>>>(q, hx, Wq, Wk, Wv);

    const int asmem = 6 * 128 * STRD * 2;   // 110592 B
    cudaFuncSetAttribute(attn_kernel, cudaFuncAttributeMaxDynamicSharedMemorySize, asmem);
    attn_kernel<<<dim3(Ss / 128, Hh, Bb), 256, asmem>>>(mask, out);
}

// round 5
// speedup vs baseline: 5.5821x; 1.3178x over previous
#include <cuda_runtime.h>
#include <cuda_fp16.h>
#include <cstdint>

#define Bb 4
#define Ss 2048
#define Ee 1024
#define Hh 16
#define Dd 64
#define STRD 72   // fp16 smem row stride: 144B = 9*16B -> conflict-free ldmatrix phases

// Projected tensors, single fp16, packed as fp16x2 words.
#define NWORDS (size_t)(Bb * Hh * Ss * Dd / 2)
__device__ uint32_t g_Qh[NWORDS];
__device__ uint32_t g_Kh[NWORDS];
__device__ uint32_t g_Vh[NWORDS];

// ---------------- helpers ----------------
__device__ __forceinline__ uint32_t pack_f16x2(float lo, float hi) {
    __half2 h = __floats2half2_rn(lo, hi);
    return *(uint32_t*)&h;
}
__device__ __forceinline__ float ex2f(float x) {
    float r; asm("ex2.approx.f32 %0, %1;" : "=f"(r) : "f"(x)); return r;
}
__device__ __forceinline__ uint32_t ex2h2(uint32_t x) {
    uint32_t r; asm("ex2.approx.f16x2 %0, %1;" : "=r"(r) : "r"(x)); return r;
}
__device__ __forceinline__ void mma16816(float c[4], const uint32_t a[4], uint32_t b0, uint32_t b1) {
    asm volatile(
        "mma.sync.aligned.m16n8k16.row.col.f32.f16.f16.f32 "
        "{%0,%1,%2,%3},{%4,%5,%6,%7},{%8,%9},{%0,%1,%2,%3};\n"
        : "+f"(c[0]), "+f"(c[1]), "+f"(c[2]), "+f"(c[3])
        : "r"(a[0]), "r"(a[1]), "r"(a[2]), "r"(a[3]), "r"(b0), "r"(b1));
}
// A-fragment (m16 x k16) from row-major tile T[row][k], stride STRD
__device__ __forceinline__ void ldmA(const unsigned short* t, int row0, int k0, uint32_t r[4]) {
    int lane = threadIdx.x & 31;
    int rr = row0 + (lane & 7) + 8 * ((lane >> 3) & 1);
    int cc = k0 + 8 * (lane >> 4);
    uint32_t a = (uint32_t)__cvta_generic_to_shared(t + rr * STRD + cc);
    asm volatile("ldmatrix.sync.aligned.m8n8.x4.shared.b16 {%0,%1,%2,%3},[%4];"
                 : "=r"(r[0]), "=r"(r[1]), "=r"(r[2]), "=r"(r[3]) : "r"(a));
}
// B-fragments (k16 x n8, n-tiles n0, n0+8) from row-major tile T[n][k]
__device__ __forceinline__ void ldmB(const unsigned short* t, int n0, int k0, uint32_t r[4]) {
    int lane = threadIdx.x & 31;
    int rr = n0 + (lane & 7) + 8 * (lane >> 4);
    int cc = k0 + 8 * ((lane >> 3) & 1);
    uint32_t a = (uint32_t)__cvta_generic_to_shared(t + rr * STRD + cc);
    asm volatile("ldmatrix.sync.aligned.m8n8.x4.shared.b16 {%0,%1,%2,%3},[%4];"
                 : "=r"(r[0]), "=r"(r[1]), "=r"(r[2]), "=r"(r[3]) : "r"(a));
}
// B-fragments for V (k16 x n8, d-tiles d0, d0+8) from row-major T[kk][d] via .trans
__device__ __forceinline__ void ldmBT(const unsigned short* t, int kk0, int d0, uint32_t r[4]) {
    int lane = threadIdx.x & 31;
    int rr = kk0 + (lane & 7) + 8 * ((lane >> 3) & 1);
    int cc = d0 + 8 * (lane >> 4);
    uint32_t a = (uint32_t)__cvta_generic_to_shared(t + rr * STRD + cc);
    asm volatile("ldmatrix.sync.aligned.m8n8.x4.trans.shared.b16 {%0,%1,%2,%3},[%4];"
                 : "=r"(r[0]), "=r"(r[1]), "=r"(r[2]), "=r"(r[3]) : "r"(a));
}
// single k16 x n8 B-fragment via .trans (for the ones-column l accumulator)
__device__ __forceinline__ void ldmBT2(const unsigned short* t, int kk0, int d0, uint32_t r[2]) {
    int lane = threadIdx.x & 31;
    int rr = kk0 + (lane & 7) + 8 * ((lane >> 3) & 1);
    uint32_t a = (uint32_t)__cvta_generic_to_shared(t + rr * STRD + d0);
    asm volatile("ldmatrix.sync.aligned.m8n8.x2.trans.shared.b16 {%0,%1},[%2];"
                 : "=r"(r[0]), "=r"(r[1]) : "r"(a));
}
__device__ __forceinline__ void cp16(unsigned short* smem_dst, const void* gsrc) {
    uint32_t s = (uint32_t)__cvta_generic_to_shared(smem_dst);
    asm volatile("cp.async.ca.shared.global [%0], [%1], 16;" :: "r"(s), "l"(gsrc));
}

// ---------------------------------------------------------------------------
// Projections: C = X @ W^T, single fp16 both sides (error budget validated).
// BM=BN=128, BK=64, 256 threads, warp owns 16 rows x 128 cols.
// ---------------------------------------------------------------------------
__global__ __launch_bounds__(256, 2) void proj_kernel(const float* __restrict__ q,
                                                      const float* __restrict__ hx,
                                                      const float* __restrict__ Wq,
                                                      const float* __restrict__ Wk,
                                                      const float* __restrict__ Wv) {
    extern __shared__ unsigned short sm16[];
    unsigned short* Xh = sm16;                 // [128][STRD]
    unsigned short* Wh = Xh + 128 * STRD;

    const int z = blockIdx.z;
    const float* X = (z == 0) ? q : hx;
    const float* W = (z == 0) ? Wq : (z == 1) ? Wk : Wv;
    uint32_t* dsth = (z == 0) ? g_Qh : (z == 1) ? g_Kh : g_Vh;

    const int tid = threadIdx.x;
    const int wid = tid >> 5, lane = tid & 31;
    const int g = lane >> 2, t4 = lane & 3;
    const int mblk = blockIdx.y, nblk = blockIdx.x;

    float c[16][4] = {};

    for (int e0 = 0; e0 < Ee; e0 += 64) {
        __syncthreads();
#pragma unroll
        for (int i = 0; i < 8; i++) {
            int slot = i * 256 + tid;          // 2048 float4 slots
            int r = slot >> 4, c4 = (slot & 15) * 4;
            float4 v = *(const float4*)(X + (size_t)(mblk * 128 + r) * Ee + e0 + c4);
            *(uint2*)(Xh + r * STRD + c4) =
                make_uint2(pack_f16x2(v.x, v.y), pack_f16x2(v.z, v.w));
            float4 w = *(const float4*)(W + (size_t)(nblk * 128 + r) * Ee + e0 + c4);
            *(uint2*)(Wh + r * STRD + c4) =
                make_uint2(pack_f16x2(w.x, w.y), pack_f16x2(w.z, w.w));
        }
        __syncthreads();

#pragma unroll
        for (int ks = 0; ks < 4; ks++) {
            uint32_t ax[4];
            ldmA(Xh, wid * 16, ks * 16, ax);
#pragma unroll
            for (int nt2 = 0; nt2 < 8; nt2++) {
                uint32_t bh[4];
                ldmB(Wh, nt2 * 16, ks * 16, bh);
                mma16816(c[2 * nt2],     ax, bh[0], bh[1]);
                mma16816(c[2 * nt2 + 1], ax, bh[2], bh[3]);
            }
        }
    }

    // epilogue -> (B,H,S,D) packed fp16x2 words
    const int m0 = mblk * 128 + wid * 16 + g;
    const int b = m0 >> 11, s0 = m0 & 2047;
#pragma unroll
    for (int nt = 0; nt < 16; nt++) {
        int n = nblk * 128 + nt * 8 + 2 * t4;
        int hh = n >> 6, d = n & 63;
        size_t w0 = ((((size_t)b * Hh + hh) * Ss + s0) * Dd + d) >> 1;
        size_t w1 = ((((size_t)b * Hh + hh) * Ss + (s0 + 8)) * Dd + d) >> 1;
        dsth[w0] = pack_f16x2(c[nt][0], c[nt][1]);
        dsth[w1] = pack_f16x2(c[nt][2], c[nt][3]);
    }
}

// ---------------------------------------------------------------------------
// Flash attention, single-fp16 MMA everywhere, exp fused into f16x2 MUFU,
// row-sum l via ones-column MMA, cp.async double-buffered K/V.
// CTA = (qt: 128 q-rows, h, b); warp owns 16 q-rows -> warp-local softmax.
// ---------------------------------------------------------------------------
#define SCLOG2 0.18033688011112042f  // 0.125 * log2(e)
#define NEGBIG -1e30f
#define NKT (Ss / 128)

__global__ __launch_bounds__(256, 1) void attn_kernel(const int* __restrict__ mask,
                                                      float* __restrict__ out) {
    extern __shared__ unsigned short sm16[];
    unsigned short* Qh = sm16;                 // tiles of [128][STRD]
    unsigned short* Kb[2] = {Qh + 128 * STRD, Qh + 3 * 128 * STRD};
    unsigned short* Vb[2] = {Qh + 2 * 128 * STRD, Qh + 4 * 128 * STRD};

    const int qt = blockIdx.x, h = blockIdx.y, b = blockIdx.z;
    const int tid = threadIdx.x;
    const int wid = tid >> 5, lane = tid & 31;
    const int g = lane >> 2, t4 = lane & 3;

    const size_t bh_base = ((size_t)b * Hh + h) * Ss;
    const size_t qw = (bh_base + qt * 128) * (Dd / 2);
    const uint32_t* Kg = g_Kh + bh_base * (Dd / 2);
    const uint32_t* Vg = g_Vh + bh_base * (Dd / 2);

    // Q tile (plain loads, once per CTA)
#pragma unroll
    for (int i = 0; i < 2; i++) {
        int slot = i * 256 + tid;
        int r = slot >> 2, c = slot & 3;       // 4 int4 per row of 64 halfs... (32 words)
        *(int4*)(Qh + r * STRD + c * 16) = *(const int4*)&g_Qh[qw + r * 32 + c * 8];
        *(int4*)(Qh + r * STRD + c * 16 + 8) = *(const int4*)&g_Qh[qw + r * 32 + c * 8 + 4];
    }

    // ones in V pad columns (64..71) of BOTH buffers -> l = P @ ones via MMA
    {
        const uint32_t one2 = 0x3C003C00u;     // half(1.0) x2
        int buf = tid >> 7, r = tid & 127;
        int4 ones4 = make_int4(one2, one2, one2, one2);
        *(int4*)(Vb[buf] + r * STRD + 64) = ones4;
    }

    // async K/V tile issue: 128 rows x 8 chunks of 16B per tensor
#define ISSUE_KV(kt, buf)                                                       \
    {                                                                           \
        const uint32_t* ks_ = Kg + (size_t)(kt) * 128 * 32;                     \
        const uint32_t* vs_ = Vg + (size_t)(kt) * 128 * 32;                     \
        _Pragma("unroll")                                                       \
        for (int i_ = 0; i_ < 4; i_++) {                                        \
            int slot_ = i_ * 256 + tid;                                         \
            int r_ = slot_ >> 3, c_ = slot_ & 7;                                \
            cp16(Kb[buf] + r_ * STRD + c_ * 8, ks_ + r_ * 32 + c_ * 4);         \
            cp16(Vb[buf] + r_ * STRD + c_ * 8, vs_ + r_ * 32 + c_ * 4);         \
        }                                                                       \
        asm volatile("cp.async.commit_group;");                                 \
    }

    ISSUE_KV(0, 0);

    float o[8][4] = {};
    float lacc[4] = {};
    float mrun0 = NEGBIG, mrun1 = NEGBIG;

    const int r0 = qt * 128 + wid * 16 + g;
    const int r1 = r0 + 8;
    const int* mp0 = mask + ((size_t)b * Ss + r0) * Ss;
    const int* mp1 = mask + ((size_t)b * Ss + r1) * Ss;

    for (int kt = 0; kt < NKT; kt++) {
        if (kt + 1 < NKT) {
            ISSUE_KV(kt + 1, (kt + 1) & 1);
            asm volatile("cp.async.wait_group 1;");
        } else {
            asm volatile("cp.async.wait_group 0;");
        }
        __syncthreads();
        const unsigned short* Kt = Kb[kt & 1];
        const unsigned short* Vt = Vb[kt & 1];

        // ---- S = Qh Kh^T : 16 x 128 per warp ----
        float s[16][4] = {};
#pragma unroll
        for (int ks = 0; ks < 4; ks++) {
            uint32_t aq[4];
            ldmA(Qh, wid * 16, ks * 16, aq);
#pragma unroll
            for (int nt2 = 0; nt2 < 8; nt2++) {
                uint32_t bk[4];
                ldmB(Kt, nt2 * 16, ks * 16, bk);
                mma16816(s[2 * nt2],     aq, bk[0], bk[1]);
                mma16816(s[2 * nt2 + 1], aq, bk[2], bk[3]);
            }
        }

        // ---- mask + scale into log2 domain ----
        const int cb = kt * 128 + 2 * t4;
#pragma unroll
        for (int nt = 0; nt < 16; nt++) {
            int2 m0 = *(const int2*)(mp0 + cb + nt * 8);
            int2 m1 = *(const int2*)(mp1 + cb + nt * 8);
            s[nt][0] = m0.x ? NEGBIG : s[nt][0] * SCLOG2;
            s[nt][1] = m0.y ? NEGBIG : s[nt][1] * SCLOG2;
            s[nt][2] = m1.x ? NEGBIG : s[nt][2] * SCLOG2;
            s[nt][3] = m1.y ? NEGBIG : s[nt][3] * SCLOG2;
        }

        // ---- warp-local row max ----
        float mx0 = NEGBIG, mx1 = NEGBIG;
#pragma unroll
        for (int nt = 0; nt < 16; nt++) {
            mx0 = fmaxf(mx0, fmaxf(s[nt][0], s[nt][1]));
            mx1 = fmaxf(mx1, fmaxf(s[nt][2], s[nt][3]));
        }
        mx0 = fmaxf(mx0, __shfl_xor_sync(0xffffffffu, mx0, 1));
        mx0 = fmaxf(mx0, __shfl_xor_sync(0xffffffffu, mx0, 2));
        mx1 = fmaxf(mx1, __shfl_xor_sync(0xffffffffu, mx1, 1));
        mx1 = fmaxf(mx1, __shfl_xor_sync(0xffffffffu, mx1, 2));
        float mnew0 = fmaxf(mrun0, mx0), mnew1 = fmaxf(mrun1, mx1);
        float corr0 = ex2f(mrun0 - mnew0), corr1 = ex2f(mrun1 - mnew1);
        mrun0 = mnew0; mrun1 = mnew1;

        // rescale running accumulators (l rides along as MMA accumulator)
#pragma unroll
        for (int nd = 0; nd < 8; nd++) {
            o[nd][0] *= corr0; o[nd][1] *= corr0;
            o[nd][2] *= corr1; o[nd][3] *= corr1;
        }
        lacc[0] *= corr0; lacc[1] *= corr0;
        lacc[2] *= corr1; lacc[3] *= corr1;

        // ---- P = exp2(s - mnew) directly in f16x2 (MUFU output = A-fragment) ----
        uint32_t ph[32];
#pragma unroll
        for (int nt = 0; nt < 16; nt++) {
            ph[2 * nt]     = ex2h2(pack_f16x2(s[nt][0] - mnew0, s[nt][1] - mnew0));
            ph[2 * nt + 1] = ex2h2(pack_f16x2(s[nt][2] - mnew1, s[nt][3] - mnew1));
        }

        // ---- O += P V ; l += P @ ones (pad column) ----
#pragma unroll
        for (int ks2 = 0; ks2 < 8; ks2++) {
            const uint32_t pa[4] = {ph[4 * ks2], ph[4 * ks2 + 1], ph[4 * ks2 + 2], ph[4 * ks2 + 3]};
#pragma unroll
            for (int d2 = 0; d2 < 4; d2++) {
                uint32_t bv[4];
                ldmBT(Vt, ks2 * 16, d2 * 16, bv);
                mma16816(o[2 * d2],     pa, bv[0], bv[1]);
                mma16816(o[2 * d2 + 1], pa, bv[2], bv[3]);
            }
            uint32_t bl[2];
            ldmBT2(Vt, ks2 * 16, 64, bl);
            mma16816(lacc, pa, bl[0], bl[1]);
        }
        __syncthreads();  // all warps done with buf (kt&1) before next issue overwrites it
    }

    // ---- epilogue: normalize, write (B, S, H*D) fp32 ----
    float inv0 = 1.f / fmaxf(lacc[0], 1e-30f);
    float inv1 = 1.f / fmaxf(lacc[2], 1e-30f);
#pragma unroll
    for (int nd = 0; nd < 8; nd++) {
        int d = nd * 8 + 2 * t4;
        *(float2*)&out[((size_t)b * Ss + r0) * (Hh * Dd) + h * Dd + d] =
            make_float2(o[nd][0] * inv0, o[nd][1] * inv0);
        *(float2*)&out[((size_t)b * Ss + r1) * (Hh * Dd) + h * Dd + d] =
            make_float2(o[nd][2] * inv1, o[nd][3] * inv1);
    }
}

// ---------------------------------------------------------------------------
extern "C" void kernel_launch(void* const* d_in, const int* in_sizes, int n_in,
                              void* d_out, int out_size) {
    const float* q  = (const float*)d_in[0];
    const float* hx = (const float*)d_in[1];
    const int* mask = (const int*)d_in[2];
    const float* Wq = (const float*)d_in[3];
    const float* Wk = (const float*)d_in[4];
    const float* Wv = (const float*)d_in[5];
    float* out = (float*)d_out;

    const int psmem = 2 * 128 * STRD * 2;   // 36864 B
    cudaFuncSetAttribute(proj_kernel, cudaFuncAttributeMaxDynamicSharedMemorySize, psmem);
    proj_kernel<<<dim3(Hh * Dd / 128, Bb * Ss / 128, 3), 256, psmem>>>(q, hx, Wq, Wk, Wv);

    const int asmem = 5 * 128 * STRD * 2;   // 92160 B
    cudaFuncSetAttribute(attn_kernel, cudaFuncAttributeMaxDynamicSharedMemorySize, asmem);
    attn_kernel<<<dim3(Ss / 128, Hh, Bb), 256, asmem>>>(mask, out);
}

// round 6
// speedup vs baseline: 6.8546x; 1.2280x over previous
#include <cuda_runtime.h>
#include <cuda_fp16.h>
#include <cstdint>

#define Bb 4
#define Ss 2048
#define Ee 1024
#define Hh 16
#define Dd 64
#define STRD 72   // fp16 smem row stride: 144B = 9*16B -> conflict-free ldmatrix phases

// fp16 copies of inputs (prep kernel), packed fp16x2 words
__device__ uint32_t g_Xq[(size_t)Bb * Ss * Ee / 2];
__device__ uint32_t g_Xh[(size_t)Bb * Ss * Ee / 2];
__device__ uint32_t g_Wq16[(size_t)Hh * Dd * Ee / 2];
__device__ uint32_t g_Wk16[(size_t)Hh * Dd * Ee / 2];
__device__ uint32_t g_Wv16[(size_t)Hh * Dd * Ee / 2];
// bit-packed mask: word w64 covers cols [w64*64, w64*64+64) of one (b, s) row
__device__ unsigned long long g_pm64[(size_t)Bb * Ss * Ss / 64];
// projected Q/K/V, fp16 packed, (B,H,S,D)
#define NWORDS (size_t)(Bb * Hh * Ss * Dd / 2)
__device__ uint32_t g_Qh[NWORDS];
__device__ uint32_t g_Kh[NWORDS];
__device__ uint32_t g_Vh[NWORDS];

// ---------------- helpers ----------------
__device__ __forceinline__ uint32_t pack_f16x2(float lo, float hi) {
    __half2 h = __floats2half2_rn(lo, hi);
    return *(uint32_t*)&h;
}
__device__ __forceinline__ float ex2f(float x) {
    float r; asm("ex2.approx.f32 %0, %1;" : "=f"(r) : "f"(x)); return r;
}
__device__ __forceinline__ uint32_t ex2h2(uint32_t x) {
    uint32_t r; asm("ex2.approx.f16x2 %0, %1;" : "=r"(r) : "r"(x)); return r;
}
__device__ __forceinline__ void mma16816(float c[4], const uint32_t a[4], uint32_t b0, uint32_t b1) {
    asm volatile(
        "mma.sync.aligned.m16n8k16.row.col.f32.f16.f16.f32 "
        "{%0,%1,%2,%3},{%4,%5,%6,%7},{%8,%9},{%0,%1,%2,%3};\n"
        : "+f"(c[0]), "+f"(c[1]), "+f"(c[2]), "+f"(c[3])
        : "r"(a[0]), "r"(a[1]), "r"(a[2]), "r"(a[3]), "r"(b0), "r"(b1));
}
__device__ __forceinline__ void ldmA(const unsigned short* t, int row0, int k0, uint32_t r[4]) {
    int lane = threadIdx.x & 31;
    int rr = row0 + (lane & 7) + 8 * ((lane >> 3) & 1);
    int cc = k0 + 8 * (lane >> 4);
    uint32_t a = (uint32_t)__cvta_generic_to_shared(t + rr * STRD + cc);
    asm volatile("ldmatrix.sync.aligned.m8n8.x4.shared.b16 {%0,%1,%2,%3},[%4];"
                 : "=r"(r[0]), "=r"(r[1]), "=r"(r[2]), "=r"(r[3]) : "r"(a));
}
__device__ __forceinline__ void ldmB(const unsigned short* t, int n0, int k0, uint32_t r[4]) {
    int lane = threadIdx.x & 31;
    int rr = n0 + (lane & 7) + 8 * (lane >> 4);
    int cc = k0 + 8 * ((lane >> 3) & 1);
    uint32_t a = (uint32_t)__cvta_generic_to_shared(t + rr * STRD + cc);
    asm volatile("ldmatrix.sync.aligned.m8n8.x4.shared.b16 {%0,%1,%2,%3},[%4];"
                 : "=r"(r[0]), "=r"(r[1]), "=r"(r[2]), "=r"(r[3]) : "r"(a));
}
__device__ __forceinline__ void ldmBT(const unsigned short* t, int kk0, int d0, uint32_t r[4]) {
    int lane = threadIdx.x & 31;
    int rr = kk0 + (lane & 7) + 8 * ((lane >> 3) & 1);
    int cc = d0 + 8 * (lane >> 4);
    uint32_t a = (uint32_t)__cvta_generic_to_shared(t + rr * STRD + cc);
    asm volatile("ldmatrix.sync.aligned.m8n8.x4.trans.shared.b16 {%0,%1,%2,%3},[%4];"
                 : "=r"(r[0]), "=r"(r[1]), "=r"(r[2]), "=r"(r[3]) : "r"(a));
}
__device__ __forceinline__ void ldmBT2(const unsigned short* t, int kk0, int d0, uint32_t r[2]) {
    int lane = threadIdx.x & 31;
    int rr = kk0 + (lane & 7) + 8 * ((lane >> 3) & 1);
    uint32_t a = (uint32_t)__cvta_generic_to_shared(t + rr * STRD + d0);
    asm volatile("ldmatrix.sync.aligned.m8n8.x2.trans.shared.b16 {%0,%1},[%2];"
                 : "=r"(r[0]), "=r"(r[1]) : "r"(a));
}
__device__ __forceinline__ void cp16(unsigned short* smem_dst, const void* gsrc) {
    uint32_t s = (uint32_t)__cvta_generic_to_shared(smem_dst);
    asm volatile("cp.async.ca.shared.global [%0], [%1], 16;" :: "r"(s), "l"(gsrc));
}

// ---------------------------------------------------------------------------
// Prep: fp32 -> fp16 packed copies of q, hx, Wq, Wk, Wv
// ---------------------------------------------------------------------------
__global__ __launch_bounds__(256) void prep_f16(const float* __restrict__ q,
                                                const float* __restrict__ hx,
                                                const float* __restrict__ Wq,
                                                const float* __restrict__ Wk,
                                                const float* __restrict__ Wv) {
    const int z = blockIdx.y;
    const float* src = (z == 0) ? q : (z == 1) ? hx : (z == 2) ? Wq : (z == 3) ? Wk : Wv;
    uint32_t* dst = (z == 0) ? g_Xq : (z == 1) ? g_Xh : (z == 2) ? g_Wq16 : (z == 3) ? g_Wk16 : g_Wv16;
    size_t n = (z < 2) ? ((size_t)Bb * Ss * Ee / 2) : ((size_t)Hh * Dd * Ee / 2);
    size_t stride = (size_t)gridDim.x * blockDim.x;
    for (size_t i = (size_t)blockIdx.x * blockDim.x + threadIdx.x; i < n; i += stride) {
        float2 v = ((const float2*)src)[i];
        dst[i] = pack_f16x2(v.x, v.y);
    }
}

// mask (int32, nonzero = disallowed) -> bitmask, 64 cols per uint64
__global__ __launch_bounds__(256) void prep_mask(const int* __restrict__ mask) {
    int lane = threadIdx.x & 31;
    size_t gw = ((size_t)blockIdx.x * blockDim.x + threadIdx.x) >> 5;
    size_t nw = ((size_t)gridDim.x * blockDim.x) >> 5;
    const size_t NW = (size_t)Bb * Ss * Ss / 64;
    for (size_t w = gw; w < NW; w += nw) {
        const int* p = mask + w * 64;
        uint32_t b0 = __ballot_sync(0xffffffffu, p[lane] != 0);
        uint32_t b1 = __ballot_sync(0xffffffffu, p[lane + 32] != 0);
        if (lane == 0)
            g_pm64[w] = (unsigned long long)b0 | ((unsigned long long)b1 << 32);
    }
}

// ---------------------------------------------------------------------------
// Projections: C = X @ W^T (fp16 in, fp16 packed out, (B,H,S,D)).
// BM=128(X rows), BN=256(W rows), BK=64. 8 warps as 2(m64) x 4(n64).
// Double-buffered cp.async.
// ---------------------------------------------------------------------------
__global__ __launch_bounds__(256, 1) void proj_kernel() {
    extern __shared__ unsigned short sm16[];
    // stage layout: X[128][STRD] then W[256][STRD]; stage stride 384*STRD
    const int z = blockIdx.z;
    const uint32_t* X = (z == 0) ? g_Xq : g_Xh;
    const uint32_t* W = (z == 0) ? g_Wq16 : (z == 1) ? g_Wk16 : g_Wv16;
    uint32_t* dst = (z == 0) ? g_Qh : (z == 1) ? g_Kh : g_Vh;

    const int tid = threadIdx.x;
    const int wid = tid >> 5, lane = tid & 31;
    const int g = lane >> 2, t4 = lane & 3;
    const int wm = wid >> 2, wn = wid & 3;
    const int mbase = blockIdx.y * 128;
    const int nbase = blockIdx.x * 256;

#define PSTAGE(st) (sm16 + (st) * 384 * STRD)
#define PROJ_ISSUE(et, st)                                                        \
    {                                                                             \
        unsigned short* xs_ = PSTAGE(st);                                         \
        unsigned short* ws_ = PSTAGE(st) + 128 * STRD;                            \
        int ew_ = (et) * 32; /* word offset of e-chunk */                         \
        _Pragma("unroll")                                                         \
        for (int i_ = 0; i_ < 12; i_++) {                                         \
            int slot_ = i_ * 256 + tid;                                           \
            if (slot_ < 1024) {                                                   \
                int r_ = slot_ >> 3, c_ = slot_ & 7;                              \
                cp16(xs_ + r_ * STRD + c_ * 8,                                    \
                     X + (size_t)(mbase + r_) * 512 + ew_ + c_ * 4);              \
            } else {                                                              \
                int s2_ = slot_ - 1024;                                           \
                int r_ = s2_ >> 3, c_ = s2_ & 7;                                  \
                cp16(ws_ + r_ * STRD + c_ * 8,                                    \
                     W + (size_t)(nbase + r_) * 512 + ew_ + c_ * 4);              \
            }                                                                     \
        }                                                                         \
        asm volatile("cp.async.commit_group;");                                   \
    }

    float c[4][8][4] = {};
    PROJ_ISSUE(0, 0);

    for (int et = 0; et < 16; et++) {
        if (et + 1 < 16) { PROJ_ISSUE(et + 1, (et + 1) & 1); }
        else { asm volatile("cp.async.commit_group;"); }
        asm volatile("cp.async.wait_group 1;");
        __syncthreads();
        const unsigned short* Xs = PSTAGE(et & 1);
        const unsigned short* Ws = PSTAGE(et & 1) + 128 * STRD;

#pragma unroll
        for (int ks = 0; ks < 4; ks++) {
            uint32_t ax[4][4], bw[4][4];
#pragma unroll
            for (int mt = 0; mt < 4; mt++) ldmA(Xs, wm * 64 + mt * 16, ks * 16, ax[mt]);
#pragma unroll
            for (int nt2 = 0; nt2 < 4; nt2++) ldmB(Ws, wn * 64 + nt2 * 16, ks * 16, bw[nt2]);
#pragma unroll
            for (int mt = 0; mt < 4; mt++)
#pragma unroll
                for (int nt2 = 0; nt2 < 4; nt2++) {
                    mma16816(c[mt][2 * nt2],     ax[mt], bw[nt2][0], bw[nt2][1]);
                    mma16816(c[mt][2 * nt2 + 1], ax[mt], bw[nt2][2], bw[nt2][3]);
                }
        }
        __syncthreads();
    }

    // epilogue: n64 block == one head; write packed fp16x2 words to (B,H,S,D)
    const int h = blockIdx.x * 4 + wn;
#pragma unroll
    for (int mt = 0; mt < 4; mt++) {
        int m0 = mbase + wm * 64 + mt * 16 + g;
        int b = m0 >> 11, s0 = m0 & 2047;
        size_t base0 = (((size_t)b * Hh + h) * Ss + s0) * (Dd / 2);
        size_t base1 = base0 + 8 * (Dd / 2);
#pragma unroll
        for (int nt = 0; nt < 8; nt++) {
            int dw = nt * 4 + t4;   // d/2
            dst[base0 + dw] = pack_f16x2(c[mt][nt][0], c[mt][nt][1]);
            dst[base1 + dw] = pack_f16x2(c[mt][nt][2], c[mt][nt][3]);
        }
    }
}

// ---------------------------------------------------------------------------
// Flash attention. CTA = 256 q-rows x (h, b); 8 warps, warp owns 32 q-rows.
// K-tile width 64. Q fragments live in registers for the whole kernel.
// 4-stage cp.async pipeline for K/V. Bitmask. l via ones-column MMA.
// ---------------------------------------------------------------------------
#define SCLOG2 0.18033688011112042f  // 0.125 * log2(e)
#define NEGBIG -1e30f
#define NKT (Ss / 64)                 // 32 k-tiles
#define ASTAGE(st) (sm16 + (st) * 128 * STRD)   // K at +0 (64 rows), V at +64*STRD

__global__ __launch_bounds__(256, 1) void attn_kernel(float* __restrict__ out) {
    extern __shared__ unsigned short sm16[];

    const int qt = blockIdx.x, h = blockIdx.y, b = blockIdx.z;
    const int tid = threadIdx.x;
    const int wid = tid >> 5, lane = tid & 31;
    const int g = lane >> 2, t4 = lane & 3;

    const size_t bh_base = ((size_t)b * Hh + h) * Ss;
    const uint32_t* Kg = g_Kh + bh_base * (Dd / 2);
    const uint32_t* Vg = g_Vh + bh_base * (Dd / 2);

    // ---- stage Q into (aliased) smem, pull fragments to registers ----
    {
        const uint32_t* Qg = g_Qh + (bh_base + qt * 256) * (Dd / 2);
#pragma unroll
        for (int i = 0; i < 8; i++) {
            int slot = i * 256 + tid;           // 256 rows x 8 chunks
            int r = slot >> 3, c = slot & 7;
            *(int4*)(sm16 + r * STRD + c * 8) = *(const int4*)&Qg[r * 32 + c * 4];
        }
    }
    __syncthreads();
    uint32_t aq[2][4][4];
#pragma unroll
    for (int mh = 0; mh < 2; mh++)
#pragma unroll
        for (int ks = 0; ks < 4; ks++)
            ldmA(sm16, wid * 32 + mh * 16, ks * 16, aq[mh][ks]);
    __syncthreads();   // everyone done reading Q before pipeline overwrites

    // ones in V pad cols (64..71) of all 4 stages (cp.async never touches pad)
    {
        const uint32_t one2 = 0x3C003C00u;
        int st = tid >> 6, r = tid & 63;
        *(int4*)(ASTAGE(st) + 64 * STRD + r * STRD + 64) =
            make_int4(one2, one2, one2, one2);
    }

#define ATTN_ISSUE(kt, st)                                                        \
    {                                                                             \
        const uint32_t* ks_ = Kg + (size_t)(kt) * 64 * 32;                        \
        const uint32_t* vs_ = Vg + (size_t)(kt) * 64 * 32;                        \
        unsigned short* kb_ = ASTAGE(st);                                         \
        unsigned short* vb_ = ASTAGE(st) + 64 * STRD;                             \
        _Pragma("unroll")                                                         \
        for (int i_ = 0; i_ < 4; i_++) {                                          \
            int slot_ = i_ * 256 + tid;                                           \
            int r_ = (slot_ >> 3) & 63, c_ = slot_ & 7;                           \
            if (slot_ < 512) cp16(kb_ + r_ * STRD + c_ * 8, ks_ + r_ * 32 + c_ * 4); \
            else             cp16(vb_ + r_ * STRD + c_ * 8, vs_ + r_ * 32 + c_ * 4); \
        }                                                                         \
        asm volatile("cp.async.commit_group;");                                   \
    }

    ATTN_ISSUE(0, 0);
    ATTN_ISSUE(1, 1);
    ATTN_ISSUE(2, 2);

    float o[2][8][4] = {};
    float lacc[2][4] = {};
    float mr[4] = {NEGBIG, NEGBIG, NEGBIG, NEGBIG};   // rows g, g+8, g+16, g+24

    const int r0 = qt * 256 + wid * 32 + g;
    const unsigned long long* pmr = g_pm64 + ((size_t)b * Ss + r0) * (Ss / 64);

    for (int kt = 0; kt < NKT; kt++) {
        if (kt + 3 < NKT) { ATTN_ISSUE(kt + 3, (kt + 3) & 3); }
        else { asm volatile("cp.async.commit_group;"); }

        // prefetch mask bits for this tile (rows g, g+8, g+16, g+24)
        unsigned long long mA = pmr[kt];
        unsigned long long mB = pmr[kt + 8 * (Ss / 64)];
        unsigned long long mC = pmr[kt + 16 * (Ss / 64)];
        unsigned long long mD = pmr[kt + 24 * (Ss / 64)];

        asm volatile("cp.async.wait_group 3;");
        __syncthreads();
        const unsigned short* Kt = ASTAGE(kt & 3);
        const unsigned short* Vt = ASTAGE(kt & 3) + 64 * STRD;

        // ---- S = Q K^T : 32 x 64 per warp ----
        float s[2][8][4] = {};
#pragma unroll
        for (int ks = 0; ks < 4; ks++) {
            uint32_t bk[4][4];
#pragma unroll
            for (int nt2 = 0; nt2 < 4; nt2++) ldmB(Kt, nt2 * 16, ks * 16, bk[nt2]);
#pragma unroll
            for (int mh = 0; mh < 2; mh++)
#pragma unroll
                for (int nt2 = 0; nt2 < 4; nt2++) {
                    mma16816(s[mh][2 * nt2],     aq[mh][ks], bk[nt2][0], bk[nt2][1]);
                    mma16816(s[mh][2 * nt2 + 1], aq[mh][ks], bk[nt2][2], bk[nt2][3]);
                }
        }

        // ---- mask (bit-packed) + scale into log2 domain ----
#pragma unroll
        for (int nt = 0; nt < 8; nt++) {
            int sh = nt * 8 + 2 * t4;
            uint32_t a2 = (uint32_t)(mA >> sh) & 3u;
            uint32_t b2 = (uint32_t)(mB >> sh) & 3u;
            uint32_t c2 = (uint32_t)(mC >> sh) & 3u;
            uint32_t d2 = (uint32_t)(mD >> sh) & 3u;
            s[0][nt][0] = (a2 & 1) ? NEGBIG : s[0][nt][0] * SCLOG2;
            s[0][nt][1] = (a2 & 2) ? NEGBIG : s[0][nt][1] * SCLOG2;
            s[0][nt][2] = (b2 & 1) ? NEGBIG : s[0][nt][2] * SCLOG2;
            s[0][nt][3] = (b2 & 2) ? NEGBIG : s[0][nt][3] * SCLOG2;
            s[1][nt][0] = (c2 & 1) ? NEGBIG : s[1][nt][0] * SCLOG2;
            s[1][nt][1] = (c2 & 2) ? NEGBIG : s[1][nt][1] * SCLOG2;
            s[1][nt][2] = (d2 & 1) ? NEGBIG : s[1][nt][2] * SCLOG2;
            s[1][nt][3] = (d2 & 2) ? NEGBIG : s[1][nt][3] * SCLOG2;
        }

        // ---- online softmax, 4 row-groups, quad-local shuffles ----
        float mx[4] = {NEGBIG, NEGBIG, NEGBIG, NEGBIG};
#pragma unroll
        for (int nt = 0; nt < 8; nt++) {
            mx[0] = fmaxf(mx[0], fmaxf(s[0][nt][0], s[0][nt][1]));
            mx[1] = fmaxf(mx[1], fmaxf(s[0][nt][2], s[0][nt][3]));
            mx[2] = fmaxf(mx[2], fmaxf(s[1][nt][0], s[1][nt][1]));
            mx[3] = fmaxf(mx[3], fmaxf(s[1][nt][2], s[1][nt][3]));
        }
        float corr[4];
#pragma unroll
        for (int rgi = 0; rgi < 4; rgi++) {
            mx[rgi] = fmaxf(mx[rgi], __shfl_xor_sync(0xffffffffu, mx[rgi], 1));
            mx[rgi] = fmaxf(mx[rgi], __shfl_xor_sync(0xffffffffu, mx[rgi], 2));
            float mn = fmaxf(mr[rgi], mx[rgi]);
            corr[rgi] = ex2f(mr[rgi] - mn);
            mr[rgi] = mn;
        }
#pragma unroll
        for (int nd = 0; nd < 8; nd++) {
            o[0][nd][0] *= corr[0]; o[0][nd][1] *= corr[0];
            o[0][nd][2] *= corr[1]; o[0][nd][3] *= corr[1];
            o[1][nd][0] *= corr[2]; o[1][nd][1] *= corr[2];
            o[1][nd][2] *= corr[3]; o[1][nd][3] *= corr[3];
        }
        lacc[0][0] *= corr[0]; lacc[0][1] *= corr[0];
        lacc[0][2] *= corr[1]; lacc[0][3] *= corr[1];
        lacc[1][0] *= corr[2]; lacc[1][1] *= corr[2];
        lacc[1][2] *= corr[3]; lacc[1][3] *= corr[3];

        // ---- P = exp2(s - m) in f16x2; MUFU output = MMA A-fragment ----
        uint32_t pa[2][4][4];
#pragma unroll
        for (int mh = 0; mh < 2; mh++) {
            float mnA = mr[2 * mh], mnB = mr[2 * mh + 1];
#pragma unroll
            for (int ks2 = 0; ks2 < 4; ks2++) {
                pa[mh][ks2][0] = ex2h2(pack_f16x2(s[mh][2 * ks2][0] - mnA, s[mh][2 * ks2][1] - mnA));
                pa[mh][ks2][1] = ex2h2(pack_f16x2(s[mh][2 * ks2][2] - mnB, s[mh][2 * ks2][3] - mnB));
                pa[mh][ks2][2] = ex2h2(pack_f16x2(s[mh][2 * ks2 + 1][0] - mnA, s[mh][2 * ks2 + 1][1] - mnA));
                pa[mh][ks2][3] = ex2h2(pack_f16x2(s[mh][2 * ks2 + 1][2] - mnB, s[mh][2 * ks2 + 1][3] - mnB));
            }
        }

        // ---- O += P V ; l += P @ ones ----
#pragma unroll
        for (int ks2 = 0; ks2 < 4; ks2++) {
            uint32_t bv[4][4], bl[2];
#pragma unroll
            for (int d2 = 0; d2 < 4; d2++) ldmBT(Vt, ks2 * 16, d2 * 16, bv[d2]);
            ldmBT2(Vt, ks2 * 16, 64, bl);
#pragma unroll
            for (int mh = 0; mh < 2; mh++) {
#pragma unroll
                for (int d2 = 0; d2 < 4; d2++) {
                    mma16816(o[mh][2 * d2],     pa[mh][ks2], bv[d2][0], bv[d2][1]);
                    mma16816(o[mh][2 * d2 + 1], pa[mh][ks2], bv[d2][2], bv[d2][3]);
                }
                mma16816(lacc[mh], pa[mh][ks2], bl[0], bl[1]);
            }
        }
        __syncthreads();  // all warps done with stage (kt&3) before re-issue
    }

    // ---- epilogue: normalize, write (B, S, H*D) fp32 ----
#pragma unroll
    for (int mh = 0; mh < 2; mh++) {
        float invA = 1.f / fmaxf(lacc[mh][0], 1e-30f);
        float invB = 1.f / fmaxf(lacc[mh][2], 1e-30f);
        int rA = r0 + 16 * mh, rB = rA + 8;
        float* oA = out + ((size_t)b * Ss + rA) * (Hh * Dd) + h * Dd;
        float* oB = out + ((size_t)b * Ss + rB) * (Hh * Dd) + h * Dd;
#pragma unroll
        for (int nd = 0; nd < 8; nd++) {
            int d = nd * 8 + 2 * t4;
            *(float2*)&oA[d] = make_float2(o[mh][nd][0] * invA, o[mh][nd][1] * invA);
            *(float2*)&oB[d] = make_float2(o[mh][nd][2] * invB, o[mh][nd][3] * invB);
        }
    }
}

// ---------------------------------------------------------------------------
extern "C" void kernel_launch(void* const* d_in, const int* in_sizes, int n_in,
                              void* d_out, int out_size) {
    const float* q  = (const float*)d_in[0];
    const float* hx = (const float*)d_in[1];
    const int* mask = (const int*)d_in[2];
    const float* Wq = (const float*)d_in[3];
    const float* Wk = (const float*)d_in[4];
    const float* Wv = (const float*)d_in[5];
    float* out = (float*)d_out;

    prep_f16<<<dim3(4096, 5), 256>>>(q, hx, Wq, Wk, Wv);
    prep_mask<<<2048, 256>>>(mask);

    const int psmem = 2 * 384 * STRD * 2;   // 110592 B
    cudaFuncSetAttribute(proj_kernel, cudaFuncAttributeMaxDynamicSharedMemorySize, psmem);
    proj_kernel<<<dim3(Hh * Dd / 256, Bb * Ss / 128, 3), 256, psmem>>>();

    const int asmem = 4 * 128 * STRD * 2;   // 73728 B
    cudaFuncSetAttribute(attn_kernel, cudaFuncAttributeMaxDynamicSharedMemorySize, asmem);
    attn_kernel<<<dim3(Ss / 256, Hh, Bb), 256, asmem>>>(out);
}

// round 7
// speedup vs baseline: 7.7568x; 1.1316x over previous
#include <cuda_runtime.h>
#include <cuda_fp16.h>
#include <cstdint>

#define Bb 4
#define Ss 2048
#define Ee 1024
#define Hh 16
#define Dd 64
#define STRD 72   // fp16 smem row stride: 144B = 9*16B -> conflict-free ldmatrix phases

// fp16 copies of inputs (prep kernel), packed fp16x2 words
__device__ uint32_t g_Xq[(size_t)Bb * Ss * Ee / 2];
__device__ uint32_t g_Xh[(size_t)Bb * Ss * Ee / 2];
__device__ uint32_t g_Wq16[(size_t)Hh * Dd * Ee / 2];
__device__ uint32_t g_Wk16[(size_t)Hh * Dd * Ee / 2];
__device__ uint32_t g_Wv16[(size_t)Hh * Dd * Ee / 2];
// bit-packed mask: word w covers cols [w*64, w*64+64) of one (b, s) row
__device__ unsigned long long g_pm64[(size_t)Bb * Ss * Ss / 64];
// projected Q/K/V, fp16 packed, (B,H,S,D)
#define NWORDS (size_t)(Bb * Hh * Ss * Dd / 2)
__device__ uint32_t g_Qh[NWORDS];
__device__ uint32_t g_Kh[NWORDS];
__device__ uint32_t g_Vh[NWORDS];

// ---------------- helpers ----------------
__device__ __forceinline__ uint32_t pack_f16x2(float lo, float hi) {
    __half2 h = __floats2half2_rn(lo, hi);
    return *(uint32_t*)&h;
}
__device__ __forceinline__ float ex2f(float x) {
    float r; asm("ex2.approx.f32 %0, %1;" : "=f"(r) : "f"(x)); return r;
}
__device__ __forceinline__ uint32_t ex2h2(uint32_t x) {
    uint32_t r; asm("ex2.approx.f16x2 %0, %1;" : "=r"(r) : "r"(x)); return r;
}
__device__ __forceinline__ void mma16816(float c[4], const uint32_t a[4], uint32_t b0, uint32_t b1) {
    asm volatile(
        "mma.sync.aligned.m16n8k16.row.col.f32.f16.f16.f32 "
        "{%0,%1,%2,%3},{%4,%5,%6,%7},{%8,%9},{%0,%1,%2,%3};\n"
        : "+f"(c[0]), "+f"(c[1]), "+f"(c[2]), "+f"(c[3])
        : "r"(a[0]), "r"(a[1]), "r"(a[2]), "r"(a[3]), "r"(b0), "r"(b1));
}
__device__ __forceinline__ void ldmA(const unsigned short* t, int row0, int k0, uint32_t r[4]) {
    int lane = threadIdx.x & 31;
    int rr = row0 + (lane & 7) + 8 * ((lane >> 3) & 1);
    int cc = k0 + 8 * (lane >> 4);
    uint32_t a = (uint32_t)__cvta_generic_to_shared(t + rr * STRD + cc);
    asm volatile("ldmatrix.sync.aligned.m8n8.x4.shared.b16 {%0,%1,%2,%3},[%4];"
                 : "=r"(r[0]), "=r"(r[1]), "=r"(r[2]), "=r"(r[3]) : "r"(a));
}
__device__ __forceinline__ void ldmB(const unsigned short* t, int n0, int k0, uint32_t r[4]) {
    int lane = threadIdx.x & 31;
    int rr = n0 + (lane & 7) + 8 * (lane >> 4);
    int cc = k0 + 8 * ((lane >> 3) & 1);
    uint32_t a = (uint32_t)__cvta_generic_to_shared(t + rr * STRD + cc);
    asm volatile("ldmatrix.sync.aligned.m8n8.x4.shared.b16 {%0,%1,%2,%3},[%4];"
                 : "=r"(r[0]), "=r"(r[1]), "=r"(r[2]), "=r"(r[3]) : "r"(a));
}
__device__ __forceinline__ void ldmBT(const unsigned short* t, int kk0, int d0, uint32_t r[4]) {
    int lane = threadIdx.x & 31;
    int rr = kk0 + (lane & 7) + 8 * ((lane >> 3) & 1);
    int cc = d0 + 8 * (lane >> 4);
    uint32_t a = (uint32_t)__cvta_generic_to_shared(t + rr * STRD + cc);
    asm volatile("ldmatrix.sync.aligned.m8n8.x4.trans.shared.b16 {%0,%1,%2,%3},[%4];"
                 : "=r"(r[0]), "=r"(r[1]), "=r"(r[2]), "=r"(r[3]) : "r"(a));
}
__device__ __forceinline__ void ldmBT2(const unsigned short* t, int kk0, int d0, uint32_t r[2]) {
    int lane = threadIdx.x & 31;
    int rr = kk0 + (lane & 7) + 8 * ((lane >> 3) & 1);
    uint32_t a = (uint32_t)__cvta_generic_to_shared(t + rr * STRD + d0);
    asm volatile("ldmatrix.sync.aligned.m8n8.x2.trans.shared.b16 {%0,%1},[%2];"
                 : "=r"(r[0]), "=r"(r[1]) : "r"(a));
}
__device__ __forceinline__ void cp16(unsigned short* smem_dst, const void* gsrc) {
    uint32_t s = (uint32_t)__cvta_generic_to_shared(smem_dst);
    asm volatile("cp.async.ca.shared.global [%0], [%1], 16;" :: "r"(s), "l"(gsrc));
}

// ---------------------------------------------------------------------------
// Prep: fp32 -> fp16 packed copies of q, hx, Wq, Wk, Wv
// ---------------------------------------------------------------------------
__global__ __launch_bounds__(256) void prep_f16(const float* __restrict__ q,
                                                const float* __restrict__ hx,
                                                const float* __restrict__ Wq,
                                                const float* __restrict__ Wk,
                                                const float* __restrict__ Wv) {
    const int z = blockIdx.y;
    const float* src = (z == 0) ? q : (z == 1) ? hx : (z == 2) ? Wq : (z == 3) ? Wk : Wv;
    uint32_t* dst = (z == 0) ? g_Xq : (z == 1) ? g_Xh : (z == 2) ? g_Wq16 : (z == 3) ? g_Wk16 : g_Wv16;
    size_t n = (z < 2) ? ((size_t)Bb * Ss * Ee / 2) : ((size_t)Hh * Dd * Ee / 2);
    size_t stride = (size_t)gridDim.x * blockDim.x;
    for (size_t i = (size_t)blockIdx.x * blockDim.x + threadIdx.x; i < n; i += stride) {
        float2 v = ((const float2*)src)[i];
        dst[i] = pack_f16x2(v.x, v.y);
    }
}

// mask (int32, nonzero = disallowed) -> bitmask, 64 cols per uint64
__global__ __launch_bounds__(256) void prep_mask(const int* __restrict__ mask) {
    int lane = threadIdx.x & 31;
    size_t gw = ((size_t)blockIdx.x * blockDim.x + threadIdx.x) >> 5;
    size_t nw = ((size_t)gridDim.x * blockDim.x) >> 5;
    const size_t NW = (size_t)Bb * Ss * Ss / 64;
    for (size_t w = gw; w < NW; w += nw) {
        const int* p = mask + w * 64;
        uint32_t b0 = __ballot_sync(0xffffffffu, p[lane] != 0);
        uint32_t b1 = __ballot_sync(0xffffffffu, p[lane + 32] != 0);
        if (lane == 0)
            g_pm64[w] = (unsigned long long)b0 | ((unsigned long long)b1 << 32);
    }
}

// ---------------------------------------------------------------------------
// Projections: C = X @ W^T (fp16 in, fp16 packed out, (B,H,S,D)).
// BM=128, BN=128, BK=64. 128 threads, 4 warps as 2(m64) x 2(n64).
// Double-buffered cp.async. 2 CTAs/SM.
// ---------------------------------------------------------------------------
__global__ __launch_bounds__(128, 2) void proj_kernel() {
    extern __shared__ unsigned short sm16[];
    // stage layout: X[128][STRD] then W[128][STRD]; stage stride 256*STRD
    const int z = blockIdx.z;
    const uint32_t* X = (z == 0) ? g_Xq : g_Xh;
    const uint32_t* W = (z == 0) ? g_Wq16 : (z == 1) ? g_Wk16 : g_Wv16;
    uint32_t* dst = (z == 0) ? g_Qh : (z == 1) ? g_Kh : g_Vh;

    const int tid = threadIdx.x;
    const int wid = tid >> 5, lane = tid & 31;
    const int g = lane >> 2, t4 = lane & 3;
    const int wm = wid >> 1, wn = wid & 1;
    const int mbase = blockIdx.y * 128;
    const int nbase = blockIdx.x * 128;

#define PSTAGE(st) (sm16 + (st) * 256 * STRD)
#define PROJ_ISSUE(et, st)                                                        \
    {                                                                             \
        unsigned short* xs_ = PSTAGE(st);                                         \
        unsigned short* ws_ = PSTAGE(st) + 128 * STRD;                            \
        int ew_ = (et) * 32; /* word offset of e-chunk */                         \
        _Pragma("unroll")                                                         \
        for (int i_ = 0; i_ < 16; i_++) {                                         \
            int slot_ = i_ * 128 + tid;                                           \
            if (slot_ < 1024) {                                                   \
                int r_ = slot_ >> 3, c_ = slot_ & 7;                              \
                cp16(xs_ + r_ * STRD + c_ * 8,                                    \
                     X + (size_t)(mbase + r_) * 512 + ew_ + c_ * 4);              \
            } else {                                                              \
                int s2_ = slot_ - 1024;                                           \
                int r_ = s2_ >> 3, c_ = s2_ & 7;                                  \
                cp16(ws_ + r_ * STRD + c_ * 8,                                    \
                     W + (size_t)(nbase + r_) * 512 + ew_ + c_ * 4);              \
            }                                                                     \
        }                                                                         \
        asm volatile("cp.async.commit_group;");                                   \
    }

    float c[4][8][4] = {};
    PROJ_ISSUE(0, 0);

    for (int et = 0; et < 16; et++) {
        if (et + 1 < 16) { PROJ_ISSUE(et + 1, (et + 1) & 1); }
        else { asm volatile("cp.async.commit_group;"); }
        asm volatile("cp.async.wait_group 1;");
        __syncthreads();
        const unsigned short* Xs = PSTAGE(et & 1);
        const unsigned short* Ws = PSTAGE(et & 1) + 128 * STRD;

#pragma unroll
        for (int ks = 0; ks < 4; ks++) {
            uint32_t ax[4][4], bw[4][4];
#pragma unroll
            for (int mt = 0; mt < 4; mt++) ldmA(Xs, wm * 64 + mt * 16, ks * 16, ax[mt]);
#pragma unroll
            for (int nt2 = 0; nt2 < 4; nt2++) ldmB(Ws, wn * 64 + nt2 * 16, ks * 16, bw[nt2]);
#pragma unroll
            for (int mt = 0; mt < 4; mt++)
#pragma unroll
                for (int nt2 = 0; nt2 < 4; nt2++) {
                    mma16816(c[mt][2 * nt2],     ax[mt], bw[nt2][0], bw[nt2][1]);
                    mma16816(c[mt][2 * nt2 + 1], ax[mt], bw[nt2][2], bw[nt2][3]);
                }
        }
        __syncthreads();
    }

    // epilogue: each warp's n64 block == one head
    const int h = blockIdx.x * 2 + wn;
#pragma unroll
    for (int mt = 0; mt < 4; mt++) {
        int m0 = mbase + wm * 64 + mt * 16 + g;
        int b = m0 >> 11, s0 = m0 & 2047;
        size_t base0 = (((size_t)b * Hh + h) * Ss + s0) * (Dd / 2);
        size_t base1 = base0 + 8 * (Dd / 2);
#pragma unroll
        for (int nt = 0; nt < 8; nt++) {
            int dw = nt * 4 + t4;   // d/2
            dst[base0 + dw] = pack_f16x2(c[mt][nt][0], c[mt][nt][1]);
            dst[base1 + dw] = pack_f16x2(c[mt][nt][2], c[mt][nt][3]);
        }
    }
}

// ---------------------------------------------------------------------------
// Flash attention. CTA = 128 q-rows x (h, b); 4 warps, warp owns 32 q-rows.
// K-tile width 64. Q fragments live in registers for the whole kernel.
// 4-stage cp.async pipeline for K/V. Bitmask. l via ones-column MMA.
// 128 threads -> 2 CTAs/SM: independent CTAs hide each other's softmax/barrier.
// ---------------------------------------------------------------------------
#define SCLOG2 0.18033688011112042f  // 0.125 * log2(e)
#define NEGBIG -1e30f
#define NKT (Ss / 64)                 // 32 k-tiles
#define ASTAGE(st) (sm16 + (st) * 128 * STRD)   // K at +0 (64 rows), V at +64*STRD

__global__ __launch_bounds__(128, 2) void attn_kernel(float* __restrict__ out) {
    extern __shared__ unsigned short sm16[];

    const int qt = blockIdx.x, h = blockIdx.y, b = blockIdx.z;
    const int tid = threadIdx.x;
    const int wid = tid >> 5, lane = tid & 31;
    const int g = lane >> 2, t4 = lane & 3;

    const size_t bh_base = ((size_t)b * Hh + h) * Ss;
    const uint32_t* Kg = g_Kh + bh_base * (Dd / 2);
    const uint32_t* Vg = g_Vh + bh_base * (Dd / 2);

    // ---- stage Q (128 rows) into aliased smem, pull fragments to registers ----
    {
        const uint32_t* Qg = g_Qh + (bh_base + qt * 128) * (Dd / 2);
#pragma unroll
        for (int i = 0; i < 8; i++) {
            int slot = i * 128 + tid;           // 128 rows x 8 chunks
            int r = slot >> 3, c = slot & 7;
            *(int4*)(sm16 + r * STRD + c * 8) = *(const int4*)&Qg[r * 32 + c * 4];
        }
    }
    __syncthreads();
    uint32_t aq[2][4][4];
#pragma unroll
    for (int mh = 0; mh < 2; mh++)
#pragma unroll
        for (int ks = 0; ks < 4; ks++)
            ldmA(sm16, wid * 32 + mh * 16, ks * 16, aq[mh][ks]);
    __syncthreads();   // everyone done reading Q before pipeline overwrites

    // ones in V pad cols (64..71) of all 4 stages (cp.async never touches pad)
    {
        const uint32_t one2 = 0x3C003C00u;
        int4 ones4 = make_int4(one2, one2, one2, one2);
#pragma unroll
        for (int k = 0; k < 2; k++) {
            int slot = k * 128 + tid;
            int st = slot >> 6, r = slot & 63;
            *(int4*)(ASTAGE(st) + 64 * STRD + r * STRD + 64) = ones4;
        }
    }

#define ATTN_ISSUE(kt, st)                                                        \
    {                                                                             \
        const uint32_t* ks_ = Kg + (size_t)(kt) * 64 * 32;                        \
        const uint32_t* vs_ = Vg + (size_t)(kt) * 64 * 32;                        \
        unsigned short* kb_ = ASTAGE(st);                                         \
        unsigned short* vb_ = ASTAGE(st) + 64 * STRD;                             \
        _Pragma("unroll")                                                         \
        for (int i_ = 0; i_ < 8; i_++) {                                          \
            int slot_ = i_ * 128 + tid;                                           \
            int r_ = (slot_ >> 3) & 63, c_ = slot_ & 7;                           \
            if (slot_ < 512) cp16(kb_ + r_ * STRD + c_ * 8, ks_ + r_ * 32 + c_ * 4); \
            else             cp16(vb_ + r_ * STRD + c_ * 8, vs_ + r_ * 32 + c_ * 4); \
        }                                                                         \
        asm volatile("cp.async.commit_group;");                                   \
    }

    ATTN_ISSUE(0, 0);
    ATTN_ISSUE(1, 1);
    ATTN_ISSUE(2, 2);

    float o[2][8][4] = {};
    float lacc[2][4] = {};
    float mr[4] = {NEGBIG, NEGBIG, NEGBIG, NEGBIG};   // rows g, g+8, g+16, g+24

    const int r0 = qt * 128 + wid * 32 + g;
    const unsigned long long* pmr = g_pm64 + ((size_t)b * Ss + r0) * (Ss / 64);

    for (int kt = 0; kt < NKT; kt++) {
        if (kt + 3 < NKT) { ATTN_ISSUE(kt + 3, (kt + 3) & 3); }
        else { asm volatile("cp.async.commit_group;"); }

        // prefetch mask bits for this tile (rows g, g+8, g+16, g+24)
        unsigned long long mA = pmr[kt];
        unsigned long long mB = pmr[kt + 8 * (Ss / 64)];
        unsigned long long mC = pmr[kt + 16 * (Ss / 64)];
        unsigned long long mD = pmr[kt + 24 * (Ss / 64)];

        asm volatile("cp.async.wait_group 3;");
        __syncthreads();
        const unsigned short* Kt = ASTAGE(kt & 3);
        const unsigned short* Vt = ASTAGE(kt & 3) + 64 * STRD;

        // ---- S = Q K^T : 32 x 64 per warp ----
        float s[2][8][4] = {};
#pragma unroll
        for (int ks = 0; ks < 4; ks++) {
            uint32_t bk[4][4];
#pragma unroll
            for (int nt2 = 0; nt2 < 4; nt2++) ldmB(Kt, nt2 * 16, ks * 16, bk[nt2]);
#pragma unroll
            for (int mh = 0; mh < 2; mh++)
#pragma unroll
                for (int nt2 = 0; nt2 < 4; nt2++) {
                    mma16816(s[mh][2 * nt2],     aq[mh][ks], bk[nt2][0], bk[nt2][1]);
                    mma16816(s[mh][2 * nt2 + 1], aq[mh][ks], bk[nt2][2], bk[nt2][3]);
                }
        }

        // ---- mask (bit-packed) + scale into log2 domain ----
#pragma unroll
        for (int nt = 0; nt < 8; nt++) {
            int sh = nt * 8 + 2 * t4;
            uint32_t a2 = (uint32_t)(mA >> sh) & 3u;
            uint32_t b2 = (uint32_t)(mB >> sh) & 3u;
            uint32_t c2 = (uint32_t)(mC >> sh) & 3u;
            uint32_t d2 = (uint32_t)(mD >> sh) & 3u;
            s[0][nt][0] = (a2 & 1) ? NEGBIG : s[0][nt][0] * SCLOG2;
            s[0][nt][1] = (a2 & 2) ? NEGBIG : s[0][nt][1] * SCLOG2;
            s[0][nt][2] = (b2 & 1) ? NEGBIG : s[0][nt][2] * SCLOG2;
            s[0][nt][3] = (b2 & 2) ? NEGBIG : s[0][nt][3] * SCLOG2;
            s[1][nt][0] = (c2 & 1) ? NEGBIG : s[1][nt][0] * SCLOG2;
            s[1][nt][1] = (c2 & 2) ? NEGBIG : s[1][nt][1] * SCLOG2;
            s[1][nt][2] = (d2 & 1) ? NEGBIG : s[1][nt][2] * SCLOG2;
            s[1][nt][3] = (d2 & 2) ? NEGBIG : s[1][nt][3] * SCLOG2;
        }

        // ---- online softmax, 4 row-groups, quad-local shuffles ----
        float mx[4] = {NEGBIG, NEGBIG, NEGBIG, NEGBIG};
#pragma unroll
        for (int nt = 0; nt < 8; nt++) {
            mx[0] = fmaxf(mx[0], fmaxf(s[0][nt][0], s[0][nt][1]));
            mx[1] = fmaxf(mx[1], fmaxf(s[0][nt][2], s[0][nt][3]));
            mx[2] = fmaxf(mx[2], fmaxf(s[1][nt][0], s[1][nt][1]));
            mx[3] = fmaxf(mx[3], fmaxf(s[1][nt][2], s[1][nt][3]));
        }
        float corr[4];
#pragma unroll
        for (int rgi = 0; rgi < 4; rgi++) {
            mx[rgi] = fmaxf(mx[rgi], __shfl_xor_sync(0xffffffffu, mx[rgi], 1));
            mx[rgi] = fmaxf(mx[rgi], __shfl_xor_sync(0xffffffffu, mx[rgi], 2));
            float mn = fmaxf(mr[rgi], mx[rgi]);
            corr[rgi] = ex2f(mr[rgi] - mn);
            mr[rgi] = mn;
        }
#pragma unroll
        for (int nd = 0; nd < 8; nd++) {
            o[0][nd][0] *= corr[0]; o[0][nd][1] *= corr[0];
            o[0][nd][2] *= corr[1]; o[0][nd][3] *= corr[1];
            o[1][nd][0] *= corr[2]; o[1][nd][1] *= corr[2];
            o[1][nd][2] *= corr[3]; o[1][nd][3] *= corr[3];
        }
        lacc[0][0] *= corr[0]; lacc[0][1] *= corr[0];
        lacc[0][2] *= corr[1]; lacc[0][3] *= corr[1];
        lacc[1][0] *= corr[2]; lacc[1][1] *= corr[2];
        lacc[1][2] *= corr[3]; lacc[1][3] *= corr[3];

        // ---- P = exp2(s - m) in f16x2; MUFU output = MMA A-fragment ----
        uint32_t pa[2][4][4];
#pragma unroll
        for (int mh = 0; mh < 2; mh++) {
            float mnA = mr[2 * mh], mnB = mr[2 * mh + 1];
#pragma unroll
            for (int ks2 = 0; ks2 < 4; ks2++) {
                pa[mh][ks2][0] = ex2h2(pack_f16x2(s[mh][2 * ks2][0] - mnA, s[mh][2 * ks2][1] - mnA));
                pa[mh][ks2][1] = ex2h2(pack_f16x2(s[mh][2 * ks2][2] - mnB, s[mh][2 * ks2][3] - mnB));
                pa[mh][ks2][2] = ex2h2(pack_f16x2(s[mh][2 * ks2 + 1][0] - mnA, s[mh][2 * ks2 + 1][1] - mnA));
                pa[mh][ks2][3] = ex2h2(pack_f16x2(s[mh][2 * ks2 + 1][2] - mnB, s[mh][2 * ks2 + 1][3] - mnB));
            }
        }

        // ---- O += P V ; l += P @ ones ----
#pragma unroll
        for (int ks2 = 0; ks2 < 4; ks2++) {
            uint32_t bv[4][4], bl[2];
#pragma unroll
            for (int d2 = 0; d2 < 4; d2++) ldmBT(Vt, ks2 * 16, d2 * 16, bv[d2]);
            ldmBT2(Vt, ks2 * 16, 64, bl);
#pragma unroll
            for (int mh = 0; mh < 2; mh++) {
#pragma unroll
                for (int d2 = 0; d2 < 4; d2++) {
                    mma16816(o[mh][2 * d2],     pa[mh][ks2], bv[d2][0], bv[d2][1]);
                    mma16816(o[mh][2 * d2 + 1], pa[mh][ks2], bv[d2][2], bv[d2][3]);
                }
                mma16816(lacc[mh], pa[mh][ks2], bl[0], bl[1]);
            }
        }
        __syncthreads();  // all warps done with stage (kt&3) before re-issue
    }

    // ---- epilogue: normalize, write (B, S, H*D) fp32 ----
#pragma unroll
    for (int mh = 0; mh < 2; mh++) {
        float invA = 1.f / fmaxf(lacc[mh][0], 1e-30f);
        float invB = 1.f / fmaxf(lacc[mh][2], 1e-30f);
        int rA = r0 + 16 * mh, rB = rA + 8;
        float* oA = out + ((size_t)b * Ss + rA) * (Hh * Dd) + h * Dd;
        float* oB = out + ((size_t)b * Ss + rB) * (Hh * Dd) + h * Dd;
#pragma unroll
        for (int nd = 0; nd < 8; nd++) {
            int d = nd * 8 + 2 * t4;
            *(float2*)&oA[d] = make_float2(o[mh][nd][0] * invA, o[mh][nd][1] * invA);
            *(float2*)&oB[d] = make_float2(o[mh][nd][2] * invB, o[mh][nd][3] * invB);
        }
    }
}

// ---------------------------------------------------------------------------
extern "C" void kernel_launch(void* const* d_in, const int* in_sizes, int n_in,
                              void* d_out, int out_size) {
    const float* q  = (const float*)d_in[0];
    const float* hx = (const float*)d_in[1];
    const int* mask = (const int*)d_in[2];
    const float* Wq = (const float*)d_in[3];
    const float* Wk = (const float*)d_in[4];
    const float* Wv = (const float*)d_in[5];
    float* out = (float*)d_out;

    prep_f16<<<dim3(4096, 5), 256>>>(q, hx, Wq, Wk, Wv);
    prep_mask<<<2048, 256>>>(mask);

    const int psmem = 2 * 256 * STRD * 2;   // 73728 B
    cudaFuncSetAttribute(proj_kernel, cudaFuncAttributeMaxDynamicSharedMemorySize, psmem);
    proj_kernel<<<dim3(Hh * Dd / 128, Bb * Ss / 128, 3), 128, psmem>>>();

    const int asmem = 4 * 128 * STRD * 2;   // 73728 B
    cudaFuncSetAttribute(attn_kernel, cudaFuncAttributeMaxDynamicSharedMemorySize, asmem);
    attn_kernel<<<dim3(Ss / 128, Hh, Bb), 128, asmem>>>(out);
}

// round 8
// speedup vs baseline: 8.1221x; 1.0471x over previous
#include <cuda_runtime.h>
#include <cuda_fp16.h>
#include <cstdint>

#define Bb 4
#define Ss 2048
#define Ee 1024
#define Hh 16
#define Dd 64
#define STRD 72   // fp16 smem row stride: 144B = 9*16B -> conflict-free ldmatrix phases

// fp16 copies of inputs (prep kernel), packed fp16x2 words
__device__ uint32_t g_Xq[(size_t)Bb * Ss * Ee / 2];
__device__ uint32_t g_Xh[(size_t)Bb * Ss * Ee / 2];
__device__ uint32_t g_Wq16[(size_t)Hh * Dd * Ee / 2];
__device__ uint32_t g_Wk16[(size_t)Hh * Dd * Ee / 2];
__device__ uint32_t g_Wv16[(size_t)Hh * Dd * Ee / 2];
// bit-packed mask: word w covers cols [w*64, w*64+64) of one (b, s) row
__device__ unsigned long long g_pm64[(size_t)Bb * Ss * Ss / 64];
// projected Q/K/V, fp16 packed, (B,H,S,D)
#define NWORDS (size_t)(Bb * Hh * Ss * Dd / 2)
__device__ uint32_t g_Qh[NWORDS];
__device__ uint32_t g_Kh[NWORDS];
__device__ uint32_t g_Vh[NWORDS];

// ---------------- helpers ----------------
__device__ __forceinline__ uint32_t pack_f16x2(float lo, float hi) {
    __half2 h = __floats2half2_rn(lo, hi);
    return *(uint32_t*)&h;
}
__device__ __forceinline__ float ex2f(float x) {
    float r; asm("ex2.approx.f32 %0, %1;" : "=f"(r) : "f"(x)); return r;
}
__device__ __forceinline__ uint32_t ex2h2(uint32_t x) {
    uint32_t r; asm("ex2.approx.f16x2 %0, %1;" : "=r"(r) : "r"(x)); return r;
}
__device__ __forceinline__ void mma16816(float c[4], const uint32_t a[4], uint32_t b0, uint32_t b1) {
    asm volatile(
        "mma.sync.aligned.m16n8k16.row.col.f32.f16.f16.f32 "
        "{%0,%1,%2,%3},{%4,%5,%6,%7},{%8,%9},{%0,%1,%2,%3};\n"
        : "+f"(c[0]), "+f"(c[1]), "+f"(c[2]), "+f"(c[3])
        : "r"(a[0]), "r"(a[1]), "r"(a[2]), "r"(a[3]), "r"(b0), "r"(b1));
}
__device__ __forceinline__ void ldmA(const unsigned short* t, int row0, int k0, uint32_t r[4]) {
    int lane = threadIdx.x & 31;
    int rr = row0 + (lane & 7) + 8 * ((lane >> 3) & 1);
    int cc = k0 + 8 * (lane >> 4);
    uint32_t a = (uint32_t)__cvta_generic_to_shared(t + rr * STRD + cc);
    asm volatile("ldmatrix.sync.aligned.m8n8.x4.shared.b16 {%0,%1,%2,%3},[%4];"
                 : "=r"(r[0]), "=r"(r[1]), "=r"(r[2]), "=r"(r[3]) : "r"(a));
}
__device__ __forceinline__ void ldmB(const unsigned short* t, int n0, int k0, uint32_t r[4]) {
    int lane = threadIdx.x & 31;
    int rr = n0 + (lane & 7) + 8 * (lane >> 4);
    int cc = k0 + 8 * ((lane >> 3) & 1);
    uint32_t a = (uint32_t)__cvta_generic_to_shared(t + rr * STRD + cc);
    asm volatile("ldmatrix.sync.aligned.m8n8.x4.shared.b16 {%0,%1,%2,%3},[%4];"
                 : "=r"(r[0]), "=r"(r[1]), "=r"(r[2]), "=r"(r[3]) : "r"(a));
}
__device__ __forceinline__ void ldmBT(const unsigned short* t, int kk0, int d0, uint32_t r[4]) {
    int lane = threadIdx.x & 31;
    int rr = kk0 + (lane & 7) + 8 * ((lane >> 3) & 1);
    int cc = d0 + 8 * (lane >> 4);
    uint32_t a = (uint32_t)__cvta_generic_to_shared(t + rr * STRD + cc);
    asm volatile("ldmatrix.sync.aligned.m8n8.x4.trans.shared.b16 {%0,%1,%2,%3},[%4];"
                 : "=r"(r[0]), "=r"(r[1]), "=r"(r[2]), "=r"(r[3]) : "r"(a));
}
__device__ __forceinline__ void ldmBT2(const unsigned short* t, int kk0, int d0, uint32_t r[2]) {
    int lane = threadIdx.x & 31;
    int rr = kk0 + (lane & 7) + 8 * ((lane >> 3) & 1);
    uint32_t a = (uint32_t)__cvta_generic_to_shared(t + rr * STRD + d0);
    asm volatile("ldmatrix.sync.aligned.m8n8.x2.trans.shared.b16 {%0,%1},[%2];"
                 : "=r"(r[0]), "=r"(r[1]) : "r"(a));
}
__device__ __forceinline__ void cp16(unsigned short* smem_dst, const void* gsrc) {
    uint32_t s = (uint32_t)__cvta_generic_to_shared(smem_dst);
    asm volatile("cp.async.ca.shared.global [%0], [%1], 16;" :: "r"(s), "l"(gsrc));
}

// ---------------------------------------------------------------------------
// Prep: fp32 -> fp16 packed copies of q, hx, Wq, Wk, Wv
// ---------------------------------------------------------------------------
__global__ __launch_bounds__(256) void prep_f16(const float* __restrict__ q,
                                                const float* __restrict__ hx,
                                                const float* __restrict__ Wq,
                                                const float* __restrict__ Wk,
                                                const float* __restrict__ Wv) {
    const int z = blockIdx.y;
    const float* src = (z == 0) ? q : (z == 1) ? hx : (z == 2) ? Wq : (z == 3) ? Wk : Wv;
    uint32_t* dst = (z == 0) ? g_Xq : (z == 1) ? g_Xh : (z == 2) ? g_Wq16 : (z == 3) ? g_Wk16 : g_Wv16;
    size_t n = (z < 2) ? ((size_t)Bb * Ss * Ee / 2) : ((size_t)Hh * Dd * Ee / 2);
    size_t stride = (size_t)gridDim.x * blockDim.x;
    for (size_t i = (size_t)blockIdx.x * blockDim.x + threadIdx.x; i < n; i += stride) {
        float2 v = ((const float2*)src)[i];
        dst[i] = pack_f16x2(v.x, v.y);
    }
}

// mask (int32, nonzero = disallowed) -> bitmask, 64 cols per uint64
__global__ __launch_bounds__(256) void prep_mask(const int* __restrict__ mask) {
    int lane = threadIdx.x & 31;
    size_t gw = ((size_t)blockIdx.x * blockDim.x + threadIdx.x) >> 5;
    size_t nw = ((size_t)gridDim.x * blockDim.x) >> 5;
    const size_t NW = (size_t)Bb * Ss * Ss / 64;
    for (size_t w = gw; w < NW; w += nw) {
        const int* p = mask + w * 64;
        uint32_t b0 = __ballot_sync(0xffffffffu, p[lane] != 0);
        uint32_t b1 = __ballot_sync(0xffffffffu, p[lane + 32] != 0);
        if (lane == 0)
            g_pm64[w] = (unsigned long long)b0 | ((unsigned long long)b1 << 32);
    }
}

// ---------------------------------------------------------------------------
// Projections: C = X @ W^T (fp16 in, fp16 packed out, (B,H,S,D)).
// BM=128, BN=128, BK=64. 128 threads, 4 warps as 2(m64) x 2(n64).
// 3-stage cp.async pipeline, single barrier per chunk. 2 CTAs/SM.
// ---------------------------------------------------------------------------
__global__ __launch_bounds__(128, 2) void proj_kernel() {
    extern __shared__ unsigned short sm16[];
    const int z = blockIdx.z;
    const uint32_t* X = (z == 0) ? g_Xq : g_Xh;
    const uint32_t* W = (z == 0) ? g_Wq16 : (z == 1) ? g_Wk16 : g_Wv16;
    uint32_t* dst = (z == 0) ? g_Qh : (z == 1) ? g_Kh : g_Vh;

    const int tid = threadIdx.x;
    const int wid = tid >> 5, lane = tid & 31;
    const int g = lane >> 2, t4 = lane & 3;
    const int wm = wid >> 1, wn = wid & 1;
    const int mbase = blockIdx.y * 128;
    const int nbase = blockIdx.x * 128;

#define PSTAGE(st) (sm16 + (st) * 256 * STRD)
#define PROJ_ISSUE(et, st)                                                        \
    {                                                                             \
        unsigned short* xs_ = PSTAGE(st);                                         \
        unsigned short* ws_ = PSTAGE(st) + 128 * STRD;                            \
        int ew_ = (et) * 32; /* word offset of e-chunk */                         \
        _Pragma("unroll")                                                         \
        for (int i_ = 0; i_ < 16; i_++) {                                         \
            int slot_ = i_ * 128 + tid;                                           \
            if (slot_ < 1024) {                                                   \
                int r_ = slot_ >> 3, c_ = slot_ & 7;                              \
                cp16(xs_ + r_ * STRD + c_ * 8,                                    \
                     X + (size_t)(mbase + r_) * 512 + ew_ + c_ * 4);              \
            } else {                                                              \
                int s2_ = slot_ - 1024;                                           \
                int r_ = s2_ >> 3, c_ = s2_ & 7;                                  \
                cp16(ws_ + r_ * STRD + c_ * 8,                                    \
                     W + (size_t)(nbase + r_) * 512 + ew_ + c_ * 4);              \
            }                                                                     \
        }                                                                         \
        asm volatile("cp.async.commit_group;");                                   \
    }

    float c[4][8][4] = {};
    PROJ_ISSUE(0, 0);
    PROJ_ISSUE(1, 1);

    int sti = 2, stc = 0;
    for (int et = 0; et < 16; et++) {
        asm volatile("cp.async.wait_group 1;");
        __syncthreads();
        // all warps finished consuming stage (et-1) == stage sti -> safe to refill
        if (et + 2 < 16) { PROJ_ISSUE(et + 2, sti); }
        else { asm volatile("cp.async.commit_group;"); }
        sti = (sti == 2) ? 0 : sti + 1;

        const unsigned short* Xs = PSTAGE(stc);
        const unsigned short* Ws = PSTAGE(stc) + 128 * STRD;
        stc = (stc == 2) ? 0 : stc + 1;

#pragma unroll
        for (int ks = 0; ks < 4; ks++) {
            uint32_t ax[4][4], bw[4][4];
#pragma unroll
            for (int mt = 0; mt < 4; mt++) ldmA(Xs, wm * 64 + mt * 16, ks * 16, ax[mt]);
#pragma unroll
            for (int nt2 = 0; nt2 < 4; nt2++) ldmB(Ws, wn * 64 + nt2 * 16, ks * 16, bw[nt2]);
#pragma unroll
            for (int mt = 0; mt < 4; mt++)
#pragma unroll
                for (int nt2 = 0; nt2 < 4; nt2++) {
                    mma16816(c[mt][2 * nt2],     ax[mt], bw[nt2][0], bw[nt2][1]);
                    mma16816(c[mt][2 * nt2 + 1], ax[mt], bw[nt2][2], bw[nt2][3]);
                }
        }
    }

    // epilogue: each warp's n64 block == one head
    const int h = blockIdx.x * 2 + wn;
#pragma unroll
    for (int mt = 0; mt < 4; mt++) {
        int m0 = mbase + wm * 64 + mt * 16 + g;
        int b = m0 >> 11, s0 = m0 & 2047;
        size_t base0 = (((size_t)b * Hh + h) * Ss + s0) * (Dd / 2);
        size_t base1 = base0 + 8 * (Dd / 2);
#pragma unroll
        for (int nt = 0; nt < 8; nt++) {
            int dw = nt * 4 + t4;   // d/2
            dst[base0 + dw] = pack_f16x2(c[mt][nt][0], c[mt][nt][1]);
            dst[base1 + dw] = pack_f16x2(c[mt][nt][2], c[mt][nt][3]);
        }
    }
}

// ---------------------------------------------------------------------------
// Flash attention. CTA = 128 q-rows x (h, b); 4 warps, warp owns 32 q-rows.
// K-tile 64. Q in registers. 4-stage cp.async, SINGLE barrier per ktile.
// Max in raw domain; scale folded into exp fma. l via ones-column MMA.
// ---------------------------------------------------------------------------
#define SCLOG2 0.18033688011112042f  // 0.125 * log2(e)
#define NEGBIG -1e30f
#define NKT (Ss / 64)                 // 32 k-tiles
#define ASTAGE(st) (sm16 + (st) * 128 * STRD)   // K at +0 (64 rows), V at +64*STRD

__global__ __launch_bounds__(128, 2) void attn_kernel(float* __restrict__ out) {
    extern __shared__ unsigned short sm16[];

    const int qt = blockIdx.x, h = blockIdx.y, b = blockIdx.z;
    const int tid = threadIdx.x;
    const int wid = tid >> 5, lane = tid & 31;
    const int g = lane >> 2, t4 = lane & 3;

    const size_t bh_base = ((size_t)b * Hh + h) * Ss;
    const uint32_t* Kg = g_Kh + bh_base * (Dd / 2);
    const uint32_t* Vg = g_Vh + bh_base * (Dd / 2);

    // ---- stage Q (128 rows) into aliased smem, pull fragments to registers ----
    {
        const uint32_t* Qg = g_Qh + (bh_base + qt * 128) * (Dd / 2);
#pragma unroll
        for (int i = 0; i < 8; i++) {
            int slot = i * 128 + tid;
            int r = slot >> 3, c = slot & 7;
            *(int4*)(sm16 + r * STRD + c * 8) = *(const int4*)&Qg[r * 32 + c * 4];
        }
    }
    __syncthreads();
    uint32_t aq[2][4][4];
#pragma unroll
    for (int mh = 0; mh < 2; mh++)
#pragma unroll
        for (int ks = 0; ks < 4; ks++)
            ldmA(sm16, wid * 32 + mh * 16, ks * 16, aq[mh][ks]);
    __syncthreads();   // everyone done reading Q before pipeline overwrites

    // ones in V pad cols (64..71) of all 4 stages (cp.async never touches pad)
    {
        const uint32_t one2 = 0x3C003C00u;
        int4 ones4 = make_int4(one2, one2, one2, one2);
#pragma unroll
        for (int k = 0; k < 2; k++) {
            int slot = k * 128 + tid;
            int st = slot >> 6, r = slot & 63;
            *(int4*)(ASTAGE(st) + 64 * STRD + r * STRD + 64) = ones4;
        }
    }

#define ATTN_ISSUE(kt, st)                                                        \
    {                                                                             \
        const uint32_t* ks_ = Kg + (size_t)(kt) * 64 * 32;                        \
        const uint32_t* vs_ = Vg + (size_t)(kt) * 64 * 32;                        \
        unsigned short* kb_ = ASTAGE(st);                                         \
        unsigned short* vb_ = ASTAGE(st) + 64 * STRD;                             \
        _Pragma("unroll")                                                         \
        for (int i_ = 0; i_ < 8; i_++) {                                          \
            int slot_ = i_ * 128 + tid;                                           \
            int r_ = (slot_ >> 3) & 63, c_ = slot_ & 7;                           \
            if (slot_ < 512) cp16(kb_ + r_ * STRD + c_ * 8, ks_ + r_ * 32 + c_ * 4); \
            else             cp16(vb_ + r_ * STRD + c_ * 8, vs_ + r_ * 32 + c_ * 4); \
        }                                                                         \
        asm volatile("cp.async.commit_group;");                                   \
    }

    // barrier before first issues: pad writes + Q reads complete CTA-wide
    __syncthreads();
    ATTN_ISSUE(0, 0);
    ATTN_ISSUE(1, 1);
    ATTN_ISSUE(2, 2);

    float o[2][8][4] = {};
    float lacc[2][4] = {};
    float mr[4] = {NEGBIG, NEGBIG, NEGBIG, NEGBIG};   // raw-domain row maxes

    const int r0 = qt * 128 + wid * 32 + g;
    const unsigned long long* pmr = g_pm64 + ((size_t)b * Ss + r0) * (Ss / 64);

    for (int kt = 0; kt < NKT; kt++) {
        // mask bits for this tile (rows g, g+8, g+16, g+24) - load early
        unsigned long long mA = pmr[kt];
        unsigned long long mB = pmr[kt + 8 * (Ss / 64)];
        unsigned long long mC = pmr[kt + 16 * (Ss / 64)];
        unsigned long long mD = pmr[kt + 24 * (Ss / 64)];

        asm volatile("cp.async.wait_group 2;");
        __syncthreads();
        // rendezvous passed => all warps consumed tile kt-1 (stage (kt+3)&3): refill it
        if (kt + 3 < NKT) { ATTN_ISSUE(kt + 3, (kt + 3) & 3); }
        else { asm volatile("cp.async.commit_group;"); }

        const unsigned short* Kt = ASTAGE(kt & 3);
        const unsigned short* Vt = ASTAGE(kt & 3) + 64 * STRD;

        // ---- S = Q K^T : 32 x 64 per warp ----
        float s[2][8][4] = {};
#pragma unroll
        for (int ks = 0; ks < 4; ks++) {
            uint32_t bk[4][4];
#pragma unroll
            for (int nt2 = 0; nt2 < 4; nt2++) ldmB(Kt, nt2 * 16, ks * 16, bk[nt2]);
#pragma unroll
            for (int mh = 0; mh < 2; mh++)
#pragma unroll
                for (int nt2 = 0; nt2 < 4; nt2++) {
                    mma16816(s[mh][2 * nt2],     aq[mh][ks], bk[nt2][0], bk[nt2][1]);
                    mma16816(s[mh][2 * nt2 + 1], aq[mh][ks], bk[nt2][2], bk[nt2][3]);
                }
        }

        // ---- mask only (raw domain; scale folded into exp later) ----
#pragma unroll
        for (int nt = 0; nt < 8; nt++) {
            int sh = nt * 8 + 2 * t4;
            uint32_t a2 = (uint32_t)(mA >> sh) & 3u;
            uint32_t b2 = (uint32_t)(mB >> sh) & 3u;
            uint32_t c2 = (uint32_t)(mC >> sh) & 3u;
            uint32_t d2 = (uint32_t)(mD >> sh) & 3u;
            if (a2 & 1) s[0][nt][0] = NEGBIG;
            if (a2 & 2) s[0][nt][1] = NEGBIG;
            if (b2 & 1) s[0][nt][2] = NEGBIG;
            if (b2 & 2) s[0][nt][3] = NEGBIG;
            if (c2 & 1) s[1][nt][0] = NEGBIG;
            if (c2 & 2) s[1][nt][1] = NEGBIG;
            if (d2 & 1) s[1][nt][2] = NEGBIG;
            if (d2 & 2) s[1][nt][3] = NEGBIG;
        }

        // ---- online softmax, raw-domain max, 4 row-groups ----
        float mx[4] = {NEGBIG, NEGBIG, NEGBIG, NEGBIG};
#pragma unroll
        for (int nt = 0; nt < 8; nt++) {
            mx[0] = fmaxf(mx[0], fmaxf(s[0][nt][0], s[0][nt][1]));
            mx[1] = fmaxf(mx[1], fmaxf(s[0][nt][2], s[0][nt][3]));
            mx[2] = fmaxf(mx[2], fmaxf(s[1][nt][0], s[1][nt][1]));
            mx[3] = fmaxf(mx[3], fmaxf(s[1][nt][2], s[1][nt][3]));
        }
        float corr[4];
#pragma unroll
        for (int rgi = 0; rgi < 4; rgi++) {
            mx[rgi] = fmaxf(mx[rgi], __shfl_xor_sync(0xffffffffu, mx[rgi], 1));
            mx[rgi] = fmaxf(mx[rgi], __shfl_xor_sync(0xffffffffu, mx[rgi], 2));
            float mn = fmaxf(mr[rgi], mx[rgi]);
            corr[rgi] = ex2f((mr[rgi] - mn) * SCLOG2);
            mr[rgi] = mn;
        }
#pragma unroll
        for (int nd = 0; nd < 8; nd++) {
            o[0][nd][0] *= corr[0]; o[0][nd][1] *= corr[0];
            o[0][nd][2] *= corr[1]; o[0][nd][3] *= corr[1];
            o[1][nd][0] *= corr[2]; o[1][nd][1] *= corr[2];
            o[1][nd][2] *= corr[3]; o[1][nd][3] *= corr[3];
        }
        lacc[0][0] *= corr[0]; lacc[0][1] *= corr[0];
        lacc[0][2] *= corr[1]; lacc[0][3] *= corr[1];
        lacc[1][0] *= corr[2]; lacc[1][1] *= corr[2];
        lacc[1][2] *= corr[3]; lacc[1][3] *= corr[3];

        // ---- P = exp2(fma(s, SCLOG2, -m*SCLOG2)) in f16x2 ----
        float nm[4];
#pragma unroll
        for (int rgi = 0; rgi < 4; rgi++) nm[rgi] = -mr[rgi] * SCLOG2;
        uint32_t pa[2][4][4];
#pragma unroll
        for (int mh = 0; mh < 2; mh++) {
            float nmA = nm[2 * mh], nmB = nm[2 * mh + 1];
#pragma unroll
            for (int ks2 = 0; ks2 < 4; ks2++) {
                pa[mh][ks2][0] = ex2h2(pack_f16x2(fmaf(s[mh][2 * ks2][0], SCLOG2, nmA),
                                                  fmaf(s[mh][2 * ks2][1], SCLOG2, nmA)));
                pa[mh][ks2][1] = ex2h2(pack_f16x2(fmaf(s[mh][2 * ks2][2], SCLOG2, nmB),
                                                  fmaf(s[mh][2 * ks2][3], SCLOG2, nmB)));
                pa[mh][ks2][2] = ex2h2(pack_f16x2(fmaf(s[mh][2 * ks2 + 1][0], SCLOG2, nmA),
                                                  fmaf(s[mh][2 * ks2 + 1][1], SCLOG2, nmA)));
                pa[mh][ks2][3] = ex2h2(pack_f16x2(fmaf(s[mh][2 * ks2 + 1][2], SCLOG2, nmB),
                                                  fmaf(s[mh][2 * ks2 + 1][3], SCLOG2, nmB)));
            }
        }

        // ---- O += P V ; l += P @ ones ----
#pragma unroll
        for (int ks2 = 0; ks2 < 4; ks2++) {
            uint32_t bv[4][4], bl[2];
#pragma unroll
            for (int d2 = 0; d2 < 4; d2++) ldmBT(Vt, ks2 * 16, d2 * 16, bv[d2]);
            ldmBT2(Vt, ks2 * 16, 64, bl);
#pragma unroll
            for (int mh = 0; mh < 2; mh++) {
#pragma unroll
                for (int d2 = 0; d2 < 4; d2++) {
                    mma16816(o[mh][2 * d2],     pa[mh][ks2], bv[d2][0], bv[d2][1]);
                    mma16816(o[mh][2 * d2 + 1], pa[mh][ks2], bv[d2][2], bv[d2][3]);
                }
                mma16816(lacc[mh], pa[mh][ks2], bl[0], bl[1]);
            }
        }
        // no end-of-loop barrier: next iteration's rendezvous covers stage reuse
    }

    // ---- epilogue: normalize, write (B, S, H*D) fp32 ----
#pragma unroll
    for (int mh = 0; mh < 2; mh++) {
        float invA = 1.f / fmaxf(lacc[mh][0], 1e-30f);
        float invB = 1.f / fmaxf(lacc[mh][2], 1e-30f);
        int rA = r0 + 16 * mh, rB = rA + 8;
        float* oA = out + ((size_t)b * Ss + rA) * (Hh * Dd) + h * Dd;
        float* oB = out + ((size_t)b * Ss + rB) * (Hh * Dd) + h * Dd;
#pragma unroll
        for (int nd = 0; nd < 8; nd++) {
            int d = nd * 8 + 2 * t4;
            *(float2*)&oA[d] = make_float2(o[mh][nd][0] * invA, o[mh][nd][1] * invA);
            *(float2*)&oB[d] = make_float2(o[mh][nd][2] * invB, o[mh][nd][3] * invB);
        }
    }
}

// ---------------------------------------------------------------------------
extern "C" void kernel_launch(void* const* d_in, const int* in_sizes, int n_in,
                              void* d_out, int out_size) {
    const float* q  = (const float*)d_in[0];
    const float* hx = (const float*)d_in[1];
    const int* mask = (const int*)d_in[2];
    const float* Wq = (const float*)d_in[3];
    const float* Wk = (const float*)d_in[4];
    const float* Wv = (const float*)d_in[5];
    float* out = (float*)d_out;

    prep_f16<<<dim3(4096, 5), 256>>>(q, hx, Wq, Wk, Wv);
    prep_mask<<<2048, 256>>>(mask);

    const int psmem = 3 * 256 * STRD * 2;   // 110592 B (3 stages)
    cudaFuncSetAttribute(proj_kernel, cudaFuncAttributeMaxDynamicSharedMemorySize, psmem);
    proj_kernel<<<dim3(Hh * Dd / 128, Bb * Ss / 128, 3), 128, psmem>>>();

    const int asmem = 4 * 128 * STRD * 2;   // 73728 B
    cudaFuncSetAttribute(attn_kernel, cudaFuncAttributeMaxDynamicSharedMemorySize, asmem);
    attn_kernel<<<dim3(Ss / 128, Hh, Bb), 128, asmem>>>(out);
}

// round 9
// speedup vs baseline: 8.9587x; 1.1030x over previous
#include <cuda_runtime.h>
#include <cuda_fp16.h>
#include <cstdint>

#define Bb 4
#define Ss 2048
#define Ee 1024
#define Hh 16
#define Dd 64
#define STRD 72   // fp16 smem row stride: 144B = 9*16B -> conflict-free ldmatrix phases

// fp16 copies of inputs (prep kernel), packed fp16x2 words
__device__ uint32_t g_Xq[(size_t)Bb * Ss * Ee / 2];
__device__ uint32_t g_Xh[(size_t)Bb * Ss * Ee / 2];
__device__ uint32_t g_Wq16[(size_t)Hh * Dd * Ee / 2];
__device__ uint32_t g_Wk16[(size_t)Hh * Dd * Ee / 2];
__device__ uint32_t g_Wv16[(size_t)Hh * Dd * Ee / 2];
// bit-packed mask: word w covers cols [w*64, w*64+64) of one (b, s) row
__device__ unsigned long long g_pm64[(size_t)Bb * Ss * Ss / 64];
// projected Q/K/V, fp16 packed, (B,H,S,D)
#define NWORDS (size_t)(Bb * Hh * Ss * Dd / 2)
__device__ uint32_t g_Qh[NWORDS];
__device__ uint32_t g_Kh[NWORDS];
__device__ uint32_t g_Vh[NWORDS];

// ---------------- helpers ----------------
__device__ __forceinline__ uint32_t pack_f16x2(float lo, float hi) {
    __half2 h = __floats2half2_rn(lo, hi);
    return *(uint32_t*)&h;
}
__device__ __forceinline__ float ex2f(float x) {
    float r; asm("ex2.approx.f32 %0, %1;" : "=f"(r) : "f"(x)); return r;
}
__device__ __forceinline__ uint32_t ex2h2(uint32_t x) {
    uint32_t r; asm("ex2.approx.f16x2 %0, %1;" : "=r"(r) : "r"(x)); return r;
}
__device__ __forceinline__ uint32_t hmin2u(uint32_t a, uint32_t b) {
    __half2 r = __hmin2(*(__half2*)&a, *(__half2*)&b);
    return *(uint32_t*)&r;
}
__device__ __forceinline__ uint32_t hmax2u(uint32_t a, uint32_t b) {
    __half2 r = __hmax2(*(__half2*)&a, *(__half2*)&b);
    return *(uint32_t*)&r;
}
__device__ __forceinline__ uint32_t hfma2u(uint32_t a, uint32_t b, uint32_t c) {
    __half2 r = __hfma2(*(__half2*)&a, *(__half2*)&b, *(__half2*)&c);
    return *(uint32_t*)&r;
}
// f32-accum fp16 MMA
__device__ __forceinline__ void mma16816(float c[4], const uint32_t a[4], uint32_t b0, uint32_t b1) {
    asm volatile(
        "mma.sync.aligned.m16n8k16.row.col.f32.f16.f16.f32 "
        "{%0,%1,%2,%3},{%4,%5,%6,%7},{%8,%9},{%0,%1,%2,%3};\n"
        : "+f"(c[0]), "+f"(c[1]), "+f"(c[2]), "+f"(c[3])
        : "r"(a[0]), "r"(a[1]), "r"(a[2]), "r"(a[3]), "r"(b0), "r"(b1));
}
// f16-accum fp16 MMA (full rate)
__device__ __forceinline__ void mma16816h(uint32_t c[2], const uint32_t a[4], uint32_t b0, uint32_t b1) {
    asm volatile(
        "mma.sync.aligned.m16n8k16.row.col.f16.f16.f16.f16 "
        "{%0,%1},{%2,%3,%4,%5},{%6,%7},{%0,%1};\n"
        : "+r"(c[0]), "+r"(c[1])
        : "r"(a[0]), "r"(a[1]), "r"(a[2]), "r"(a[3]), "r"(b0), "r"(b1));
}
__device__ __forceinline__ void ldmA(const unsigned short* t, int row0, int k0, uint32_t r[4]) {
    int lane = threadIdx.x & 31;
    int rr = row0 + (lane & 7) + 8 * ((lane >> 3) & 1);
    int cc = k0 + 8 * (lane >> 4);
    uint32_t a = (uint32_t)__cvta_generic_to_shared(t + rr * STRD + cc);
    asm volatile("ldmatrix.sync.aligned.m8n8.x4.shared.b16 {%0,%1,%2,%3},[%4];"
                 : "=r"(r[0]), "=r"(r[1]), "=r"(r[2]), "=r"(r[3]) : "r"(a));
}
__device__ __forceinline__ void ldmB(const unsigned short* t, int n0, int k0, uint32_t r[4]) {
    int lane = threadIdx.x & 31;
    int rr = n0 + (lane & 7) + 8 * (lane >> 4);
    int cc = k0 + 8 * ((lane >> 3) & 1);
    uint32_t a = (uint32_t)__cvta_generic_to_shared(t + rr * STRD + cc);
    asm volatile("ldmatrix.sync.aligned.m8n8.x4.shared.b16 {%0,%1,%2,%3},[%4];"
                 : "=r"(r[0]), "=r"(r[1]), "=r"(r[2]), "=r"(r[3]) : "r"(a));
}
__device__ __forceinline__ void ldmBT(const unsigned short* t, int kk0, int d0, uint32_t r[4]) {
    int lane = threadIdx.x & 31;
    int rr = kk0 + (lane & 7) + 8 * ((lane >> 3) & 1);
    int cc = d0 + 8 * (lane >> 4);
    uint32_t a = (uint32_t)__cvta_generic_to_shared(t + rr * STRD + cc);
    asm volatile("ldmatrix.sync.aligned.m8n8.x4.trans.shared.b16 {%0,%1,%2,%3},[%4];"
                 : "=r"(r[0]), "=r"(r[1]), "=r"(r[2]), "=r"(r[3]) : "r"(a));
}
__device__ __forceinline__ void ldmBT2(const unsigned short* t, int kk0, int d0, uint32_t r[2]) {
    int lane = threadIdx.x & 31;
    int rr = kk0 + (lane & 7) + 8 * ((lane >> 3) & 1);
    uint32_t a = (uint32_t)__cvta_generic_to_shared(t + rr * STRD + d0);
    asm volatile("ldmatrix.sync.aligned.m8n8.x2.trans.shared.b16 {%0,%1},[%2];"
                 : "=r"(r[0]), "=r"(r[1]) : "r"(a));
}
__device__ __forceinline__ void cp16(unsigned short* smem_dst, const void* gsrc) {
    uint32_t s = (uint32_t)__cvta_generic_to_shared(smem_dst);
    asm volatile("cp.async.ca.shared.global [%0], [%1], 16;" :: "r"(s), "l"(gsrc));
}

// ---------------------------------------------------------------------------
// Prep: fp32 -> fp16 packed copies of q, hx, Wq, Wk, Wv
// ---------------------------------------------------------------------------
__global__ __launch_bounds__(256) void prep_f16(const float* __restrict__ q,
                                                const float* __restrict__ hx,
                                                const float* __restrict__ Wq,
                                                const float* __restrict__ Wk,
                                                const float* __restrict__ Wv) {
    const int z = blockIdx.y;
    const float* src = (z == 0) ? q : (z == 1) ? hx : (z == 2) ? Wq : (z == 3) ? Wk : Wv;
    uint32_t* dst = (z == 0) ? g_Xq : (z == 1) ? g_Xh : (z == 2) ? g_Wq16 : (z == 3) ? g_Wk16 : g_Wv16;
    size_t n = (z < 2) ? ((size_t)Bb * Ss * Ee / 2) : ((size_t)Hh * Dd * Ee / 2);
    size_t stride = (size_t)gridDim.x * blockDim.x;
    for (size_t i = (size_t)blockIdx.x * blockDim.x + threadIdx.x; i < n; i += stride) {
        float2 v = ((const float2*)src)[i];
        dst[i] = pack_f16x2(v.x, v.y);
    }
}

// mask (int32, nonzero = disallowed) -> bitmask, 64 cols per uint64
__global__ __launch_bounds__(256) void prep_mask(const int* __restrict__ mask) {
    int lane = threadIdx.x & 31;
    size_t gw = ((size_t)blockIdx.x * blockDim.x + threadIdx.x) >> 5;
    size_t nw = ((size_t)gridDim.x * blockDim.x) >> 5;
    const size_t NW = (size_t)Bb * Ss * Ss / 64;
    for (size_t w = gw; w < NW; w += nw) {
        const int* p = mask + w * 64;
        uint32_t b0 = __ballot_sync(0xffffffffu, p[lane] != 0);
        uint32_t b1 = __ballot_sync(0xffffffffu, p[lane + 32] != 0);
        if (lane == 0)
            g_pm64[w] = (unsigned long long)b0 | ((unsigned long long)b1 << 32);
    }
}

// ---------------------------------------------------------------------------
// Projections: C = X @ W^T (fp16 in, fp16 packed out, (B,H,S,D)).
// BM=128, BN=128, BK=64. 128 threads, 4 warps as 2(m64) x 2(n64).
// Double-buffered cp.async. 2 CTAs/SM. (round-7 proven version)
// ---------------------------------------------------------------------------
__global__ __launch_bounds__(128, 2) void proj_kernel() {
    extern __shared__ unsigned short sm16[];
    const int z = blockIdx.z;
    const uint32_t* X = (z == 0) ? g_Xq : g_Xh;
    const uint32_t* W = (z == 0) ? g_Wq16 : (z == 1) ? g_Wk16 : g_Wv16;
    uint32_t* dst = (z == 0) ? g_Qh : (z == 1) ? g_Kh : g_Vh;

    const int tid = threadIdx.x;
    const int wid = tid >> 5, lane = tid & 31;
    const int g = lane >> 2, t4 = lane & 3;
    const int wm = wid >> 1, wn = wid & 1;
    const int mbase = blockIdx.y * 128;
    const int nbase = blockIdx.x * 128;

#define PSTAGE(st) (sm16 + (st) * 256 * STRD)
#define PROJ_ISSUE(et, st)                                                        \
    {                                                                             \
        unsigned short* xs_ = PSTAGE(st);                                         \
        unsigned short* ws_ = PSTAGE(st) + 128 * STRD;                            \
        int ew_ = (et) * 32; /* word offset of e-chunk */                         \
        _Pragma("unroll")                                                         \
        for (int i_ = 0; i_ < 16; i_++) {                                         \
            int slot_ = i_ * 128 + tid;                                           \
            if (slot_ < 1024) {                                                   \
                int r_ = slot_ >> 3, c_ = slot_ & 7;                              \
                cp16(xs_ + r_ * STRD + c_ * 8,                                    \
                     X + (size_t)(mbase + r_) * 512 + ew_ + c_ * 4);              \
            } else {                                                              \
                int s2_ = slot_ - 1024;                                           \
                int r_ = s2_ >> 3, c_ = s2_ & 7;                                  \
                cp16(ws_ + r_ * STRD + c_ * 8,                                    \
                     W + (size_t)(nbase + r_) * 512 + ew_ + c_ * 4);              \
            }                                                                     \
        }                                                                         \
        asm volatile("cp.async.commit_group;");                                   \
    }

    float c[4][8][4] = {};
    PROJ_ISSUE(0, 0);

    for (int et = 0; et < 16; et++) {
        if (et + 1 < 16) { PROJ_ISSUE(et + 1, (et + 1) & 1); }
        else { asm volatile("cp.async.commit_group;"); }
        asm volatile("cp.async.wait_group 1;");
        __syncthreads();
        const unsigned short* Xs = PSTAGE(et & 1);
        const unsigned short* Ws = PSTAGE(et & 1) + 128 * STRD;

#pragma unroll
        for (int ks = 0; ks < 4; ks++) {
            uint32_t ax[4][4], bw[4][4];
#pragma unroll
            for (int mt = 0; mt < 4; mt++) ldmA(Xs, wm * 64 + mt * 16, ks * 16, ax[mt]);
#pragma unroll
            for (int nt2 = 0; nt2 < 4; nt2++) ldmB(Ws, wn * 64 + nt2 * 16, ks * 16, bw[nt2]);
#pragma unroll
            for (int mt = 0; mt < 4; mt++)
#pragma unroll
                for (int nt2 = 0; nt2 < 4; nt2++) {
                    mma16816(c[mt][2 * nt2],     ax[mt], bw[nt2][0], bw[nt2][1]);
                    mma16816(c[mt][2 * nt2 + 1], ax[mt], bw[nt2][2], bw[nt2][3]);
                }
        }
        __syncthreads();
    }

    // epilogue: each warp's n64 block == one head
    const int h = blockIdx.x * 2 + wn;
#pragma unroll
    for (int mt = 0; mt < 4; mt++) {
        int m0 = mbase + wm * 64 + mt * 16 + g;
        int b = m0 >> 11, s0 = m0 & 2047;
        size_t base0 = (((size_t)b * Hh + h) * Ss + s0) * (Dd / 2);
        size_t base1 = base0 + 8 * (Dd / 2);
#pragma unroll
        for (int nt = 0; nt < 8; nt++) {
            int dw = nt * 4 + t4;   // d/2
            dst[base0 + dw] = pack_f16x2(c[mt][nt][0], c[mt][nt][1]);
            dst[base1 + dw] = pack_f16x2(c[mt][nt][2], c[mt][nt][3]);
        }
    }
}

// ---------------------------------------------------------------------------
// Flash attention. CTA = 128 q-rows x (h, b); 4 warps, warp owns 32 q-rows.
// QK^T in f16 accumulators (full-rate HMMA, s lands in PV A-fragment layout).
// Mask = single hmin2 vs ±inf pair. exp fused f16x2. l via ones-column MMA.
// 4-stage cp.async, single barrier per ktile. Rescale skipped by warp vote
// when no row max changed (corr == 1 exactly).
// ---------------------------------------------------------------------------
#define SCLOG2 0.18033688011112042f  // 0.125 * log2(e)
#define MRINIT -30.0f
#define NKT (Ss / 64)                 // 32 k-tiles
#define ASTAGE(st) (sm16 + (st) * 128 * STRD)   // K at +0 (64 rows), V at +64*STRD

__global__ __launch_bounds__(128, 2) void attn_kernel(float* __restrict__ out) {
    extern __shared__ unsigned short sm16[];

    const int qt = blockIdx.x, h = blockIdx.y, b = blockIdx.z;
    const int tid = threadIdx.x;
    const int wid = tid >> 5, lane = tid & 31;
    const int g = lane >> 2, t4 = lane & 3;

    const size_t bh_base = ((size_t)b * Hh + h) * Ss;
    const uint32_t* Kg = g_Kh + bh_base * (Dd / 2);
    const uint32_t* Vg = g_Vh + bh_base * (Dd / 2);

    // ---- stage Q (128 rows) into aliased smem, pull fragments to registers ----
    {
        const uint32_t* Qg = g_Qh + (bh_base + qt * 128) * (Dd / 2);
#pragma unroll
        for (int i = 0; i < 8; i++) {
            int slot = i * 128 + tid;
            int r = slot >> 3, c = slot & 7;
            *(int4*)(sm16 + r * STRD + c * 8) = *(const int4*)&Qg[r * 32 + c * 4];
        }
    }
    __syncthreads();
    uint32_t aq[2][4][4];
#pragma unroll
    for (int mh = 0; mh < 2; mh++)
#pragma unroll
        for (int ks = 0; ks < 4; ks++)
            ldmA(sm16, wid * 32 + mh * 16, ks * 16, aq[mh][ks]);
    __syncthreads();   // everyone done reading Q before pipeline overwrites

    // ones in V pad cols (64..71) of all 4 stages (cp.async never touches pad)
    {
        const uint32_t one2 = 0x3C003C00u;
        int4 ones4 = make_int4(one2, one2, one2, one2);
#pragma unroll
        for (int k = 0; k < 2; k++) {
            int slot = k * 128 + tid;
            int st = slot >> 6, r = slot & 63;
            *(int4*)(ASTAGE(st) + 64 * STRD + r * STRD + 64) = ones4;
        }
    }

#define ATTN_ISSUE(kt, st)                                                        \
    {                                                                             \
        const uint32_t* ks_ = Kg + (size_t)(kt) * 64 * 32;                        \
        const uint32_t* vs_ = Vg + (size_t)(kt) * 64 * 32;                        \
        unsigned short* kb_ = ASTAGE(st);                                         \
        unsigned short* vb_ = ASTAGE(st) + 64 * STRD;                             \
        _Pragma("unroll")                                                         \
        for (int i_ = 0; i_ < 8; i_++) {                                          \
            int slot_ = i_ * 128 + tid;                                           \
            int r_ = (slot_ >> 3) & 63, c_ = slot_ & 7;                           \
            if (slot_ < 512) cp16(kb_ + r_ * STRD + c_ * 8, ks_ + r_ * 32 + c_ * 4); \
            else             cp16(vb_ + r_ * STRD + c_ * 8, vs_ + r_ * 32 + c_ * 4); \
        }                                                                         \
        asm volatile("cp.async.commit_group;");                                   \
    }

    __syncthreads();   // pad writes + Q reads complete CTA-wide
    ATTN_ISSUE(0, 0);
    ATTN_ISSUE(1, 1);
    ATTN_ISSUE(2, 2);

    float o[2][8][4] = {};
    float lacc[2][4] = {};
    float mr[4] = {MRINIT, MRINIT, MRINIT, MRINIT};

    const int r0 = qt * 128 + wid * 32 + g;
    const unsigned long long* pmr = g_pm64 + ((size_t)b * Ss + r0) * (Ss / 64);

    for (int kt = 0; kt < NKT; kt++) {
        unsigned long long mA = pmr[kt];
        unsigned long long mB = pmr[kt + 8 * (Ss / 64)];
        unsigned long long mC = pmr[kt + 16 * (Ss / 64)];
        unsigned long long mD = pmr[kt + 24 * (Ss / 64)];

        asm volatile("cp.async.wait_group 2;");
        __syncthreads();
        if (kt + 3 < NKT) { ATTN_ISSUE(kt + 3, (kt + 3) & 3); }
        else { asm volatile("cp.async.commit_group;"); }

        const unsigned short* Kt = ASTAGE(kt & 3);
        const unsigned short* Vt = ASTAGE(kt & 3) + 64 * STRD;

        // ---- S = Q K^T in f16 accum: s2[mh][nt][rp] = {2 cols} of one row ----
        uint32_t s2[2][8][2];
#pragma unroll
        for (int mh = 0; mh < 2; mh++)
#pragma unroll
            for (int nt = 0; nt < 8; nt++) { s2[mh][nt][0] = 0u; s2[mh][nt][1] = 0u; }
#pragma unroll
        for (int ks = 0; ks < 4; ks++) {
            uint32_t bk[4][4];
#pragma unroll
            for (int nt2 = 0; nt2 < 4; nt2++) ldmB(Kt, nt2 * 16, ks * 16, bk[nt2]);
#pragma unroll
            for (int mh = 0; mh < 2; mh++)
#pragma unroll
                for (int nt2 = 0; nt2 < 4; nt2++) {
                    mma16816h(s2[mh][2 * nt2],     aq[mh][ks], bk[nt2][0], bk[nt2][1]);
                    mma16816h(s2[mh][2 * nt2 + 1], aq[mh][ks], bk[nt2][2], bk[nt2][3]);
                }
        }

        // ---- mask: s = hmin2(s, {bit ? -inf : +inf}) ----
#pragma unroll
        for (int nt = 0; nt < 8; nt++) {
            int sh = nt * 8 + 2 * t4;
            uint32_t a2 = (uint32_t)(mA >> sh) & 3u;
            uint32_t b2 = (uint32_t)(mB >> sh) & 3u;
            uint32_t c2 = (uint32_t)(mC >> sh) & 3u;
            uint32_t d2 = (uint32_t)(mD >> sh) & 3u;
            s2[0][nt][0] = hmin2u(s2[0][nt][0], 0x7C007C00u | ((a2 & 1) << 15) | ((a2 & 2) << 30));
            s2[0][nt][1] = hmin2u(s2[0][nt][1], 0x7C007C00u | ((b2 & 1) << 15) | ((b2 & 2) << 30));
            s2[1][nt][0] = hmin2u(s2[1][nt][0], 0x7C007C00u | ((c2 & 1) << 15) | ((c2 & 2) << 30));
            s2[1][nt][1] = hmin2u(s2[1][nt][1], 0x7C007C00u | ((d2 & 1) << 15) | ((d2 & 2) << 30));
        }

        // ---- row max: hmax2 tree, collapse pair, quad shuffles in f32 ----
        uint32_t m2[4] = {0xFC00FC00u, 0xFC00FC00u, 0xFC00FC00u, 0xFC00FC00u};
#pragma unroll
        for (int nt = 0; nt < 8; nt++) {
            m2[0] = hmax2u(m2[0], s2[0][nt][0]);
            m2[1] = hmax2u(m2[1], s2[0][nt][1]);
            m2[2] = hmax2u(m2[2], s2[1][nt][0]);
            m2[3] = hmax2u(m2[3], s2[1][nt][1]);
        }
        bool same = true;
        float mn[4];
#pragma unroll
        for (int rgi = 0; rgi < 4; rgi++) {
            float2 f = __half22float2(*(__half2*)&m2[rgi]);
            float mx = fmaxf(f.x, f.y);
            mx = fmaxf(mx, __shfl_xor_sync(0xffffffffu, mx, 1));
            mx = fmaxf(mx, __shfl_xor_sync(0xffffffffu, mx, 2));
            mn[rgi] = fmaxf(mr[rgi], mx);
            same = same && (mn[rgi] == mr[rgi]);
        }
        // rescale only if some max moved (corr==1 exactly otherwise)
        if (!__all_sync(0xffffffffu, same)) {
            float corr[4];
#pragma unroll
            for (int rgi = 0; rgi < 4; rgi++)
                corr[rgi] = ex2f((mr[rgi] - mn[rgi]) * SCLOG2);
#pragma unroll
            for (int nd = 0; nd < 8; nd++) {
                o[0][nd][0] *= corr[0]; o[0][nd][1] *= corr[0];
                o[0][nd][2] *= corr[1]; o[0][nd][3] *= corr[1];
                o[1][nd][0] *= corr[2]; o[1][nd][1] *= corr[2];
                o[1][nd][2] *= corr[3]; o[1][nd][3] *= corr[3];
            }
            lacc[0][0] *= corr[0]; lacc[0][1] *= corr[0];
            lacc[0][2] *= corr[1]; lacc[0][3] *= corr[1];
            lacc[1][0] *= corr[2]; lacc[1][1] *= corr[2];
            lacc[1][2] *= corr[3]; lacc[1][3] *= corr[3];
        }
#pragma unroll
        for (int rgi = 0; rgi < 4; rgi++) mr[rgi] = mn[rgi];

        // ---- P = exp2(hfma2(s, sc, -m*sc)) in place (PV A-fragment layout) ----
        const uint32_t sc2 = 0x31C631C6u;   // half2(0.18033688)
        uint32_t nm2[4];
#pragma unroll
        for (int rgi = 0; rgi < 4; rgi++)
            nm2[rgi] = pack_f16x2(-mr[rgi] * SCLOG2, -mr[rgi] * SCLOG2);
#pragma unroll
        for (int mh = 0; mh < 2; mh++)
#pragma unroll
            for (int nt = 0; nt < 8; nt++) {
                s2[mh][nt][0] = ex2h2(hfma2u(s2[mh][nt][0], sc2, nm2[2 * mh]));
                s2[mh][nt][1] = ex2h2(hfma2u(s2[mh][nt][1], sc2, nm2[2 * mh + 1]));
            }

        // ---- O += P V ; l += P @ ones ----
#pragma unroll
        for (int ks2 = 0; ks2 < 4; ks2++) {
            uint32_t bv[4][4], bl[2];
#pragma unroll
            for (int d2 = 0; d2 < 4; d2++) ldmBT(Vt, ks2 * 16, d2 * 16, bv[d2]);
            ldmBT2(Vt, ks2 * 16, 64, bl);
#pragma unroll
            for (int mh = 0; mh < 2; mh++) {
                const uint32_t pa[4] = {s2[mh][2 * ks2][0], s2[mh][2 * ks2][1],
                                        s2[mh][2 * ks2 + 1][0], s2[mh][2 * ks2 + 1][1]};
#pragma unroll
                for (int d2 = 0; d2 < 4; d2++) {
                    mma16816(o[mh][2 * d2],     pa, bv[d2][0], bv[d2][1]);
                    mma16816(o[mh][2 * d2 + 1], pa, bv[d2][2], bv[d2][3]);
                }
                mma16816(lacc[mh], pa, bl[0], bl[1]);
            }
        }
        // no end-of-loop barrier: next iteration's rendezvous covers stage reuse
    }

    // ---- epilogue: normalize, write (B, S, H*D) fp32 ----
#pragma unroll
    for (int mh = 0; mh < 2; mh++) {
        float invA = 1.f / fmaxf(lacc[mh][0], 1e-30f);
        float invB = 1.f / fmaxf(lacc[mh][2], 1e-30f);
        int rA = r0 + 16 * mh, rB = rA + 8;
        float* oA = out + ((size_t)b * Ss + rA) * (Hh * Dd) + h * Dd;
        float* oB = out + ((size_t)b * Ss + rB) * (Hh * Dd) + h * Dd;
#pragma unroll
        for (int nd = 0; nd < 8; nd++) {
            int d = nd * 8 + 2 * t4;
            *(float2*)&oA[d] = make_float2(o[mh][nd][0] * invA, o[mh][nd][1] * invA);
            *(float2*)&oB[d] = make_float2(o[mh][nd][2] * invB, o[mh][nd][3] * invB);
        }
    }
}

// ---------------------------------------------------------------------------
extern "C" void kernel_launch(void* const* d_in, const int* in_sizes, int n_in,
                              void* d_out, int out_size) {
    const float* q  = (const float*)d_in[0];
    const float* hx = (const float*)d_in[1];
    const int* mask = (const int*)d_in[2];
    const float* Wq = (const float*)d_in[3];
    const float* Wk = (const float*)d_in[4];
    const float* Wv = (const float*)d_in[5];
    float* out = (float*)d_out;

    prep_f16<<<dim3(4096, 5), 256>>>(q, hx, Wq, Wk, Wv);
    prep_mask<<<2048, 256>>>(mask);

    const int psmem = 2 * 256 * STRD * 2;   // 73728 B (2 stages, round-7 proven)
    cudaFuncSetAttribute(proj_kernel, cudaFuncAttributeMaxDynamicSharedMemorySize, psmem);
    proj_kernel<<<dim3(Hh * Dd / 128, Bb * Ss / 128, 3), 128, psmem>>>();

    const int asmem = 4 * 128 * STRD * 2;   // 73728 B
    cudaFuncSetAttribute(attn_kernel, cudaFuncAttributeMaxDynamicSharedMemorySize, asmem);
    attn_kernel<<<dim3(Ss / 128, Hh, Bb), 128, asmem>>>(out);
}

// round 11
// speedup vs baseline: 8.9794x; 1.0023x over previous
#include <cuda_runtime.h>
#include <cuda_fp16.h>
#include <cstdint>

#define Bb 4
#define Ss 2048
#define Ee 1024
#define Hh 16
#define Dd 64
#define STRD 72   // fp16 smem row stride: 144B = 9*16B -> conflict-free ldmatrix phases

// fp16 copies of inputs (prep kernel), packed fp16x2 words
__device__ uint32_t g_Xq[(size_t)Bb * Ss * Ee / 2];
__device__ uint32_t g_Xh[(size_t)Bb * Ss * Ee / 2];
__device__ uint32_t g_Wq16[(size_t)Hh * Dd * Ee / 2];
__device__ uint32_t g_Wk16[(size_t)Hh * Dd * Ee / 2];
__device__ uint32_t g_Wv16[(size_t)Hh * Dd * Ee / 2];
// bit-packed mask: word w covers cols [w*64, w*64+64) of one (b, s) row
__device__ unsigned long long g_pm64[(size_t)Bb * Ss * Ss / 64];
// projected Q/K/V, fp16 packed, (B,H,S,D)
#define NWORDS (size_t)(Bb * Hh * Ss * Dd / 2)
__device__ uint32_t g_Qh[NWORDS];
__device__ uint32_t g_Kh[NWORDS];
__device__ uint32_t g_Vh[NWORDS];

// ---------------- helpers ----------------
__device__ __forceinline__ uint32_t pack_f16x2(float lo, float hi) {
    __half2 h = __floats2half2_rn(lo, hi);
    return *(uint32_t*)&h;
}
__device__ __forceinline__ float ex2f(float x) {
    float r; asm("ex2.approx.f32 %0, %1;" : "=f"(r) : "f"(x)); return r;
}
__device__ __forceinline__ uint32_t ex2h2(uint32_t x) {
    uint32_t r; asm("ex2.approx.f16x2 %0, %1;" : "=r"(r) : "r"(x)); return r;
}
__device__ __forceinline__ uint32_t hmin2u(uint32_t a, uint32_t b) {
    __half2 r = __hmin2(*(__half2*)&a, *(__half2*)&b);
    return *(uint32_t*)&r;
}
__device__ __forceinline__ uint32_t hmax2u(uint32_t a, uint32_t b) {
    __half2 r = __hmax2(*(__half2*)&a, *(__half2*)&b);
    return *(uint32_t*)&r;
}
__device__ __forceinline__ uint32_t hfma2u(uint32_t a, uint32_t b, uint32_t c) {
    __half2 r = __hfma2(*(__half2*)&a, *(__half2*)&b, *(__half2*)&c);
    return *(uint32_t*)&r;
}
// f32-accum fp16 MMA
__device__ __forceinline__ void mma16816(float c[4], const uint32_t a[4], uint32_t b0, uint32_t b1) {
    asm volatile(
        "mma.sync.aligned.m16n8k16.row.col.f32.f16.f16.f32 "
        "{%0,%1,%2,%3},{%4,%5,%6,%7},{%8,%9},{%0,%1,%2,%3};\n"
        : "+f"(c[0]), "+f"(c[1]), "+f"(c[2]), "+f"(c[3])
        : "r"(a[0]), "r"(a[1]), "r"(a[2]), "r"(a[3]), "r"(b0), "r"(b1));
}
// f16-accum fp16 MMA (full rate)
__device__ __forceinline__ void mma16816h(uint32_t c[2], const uint32_t a[4], uint32_t b0, uint32_t b1) {
    asm volatile(
        "mma.sync.aligned.m16n8k16.row.col.f16.f16.f16.f16 "
        "{%0,%1},{%2,%3,%4,%5},{%6,%7},{%0,%1};\n"
        : "+r"(c[0]), "+r"(c[1])
        : "r"(a[0]), "r"(a[1]), "r"(a[2]), "r"(a[3]), "r"(b0), "r"(b1));
}
__device__ __forceinline__ void ldmA(const unsigned short* t, int row0, int k0, uint32_t r[4]) {
    int lane = threadIdx.x & 31;
    int rr = row0 + (lane & 7) + 8 * ((lane >> 3) & 1);
    int cc = k0 + 8 * (lane >> 4);
    uint32_t a = (uint32_t)__cvta_generic_to_shared(t + rr * STRD + cc);
    asm volatile("ldmatrix.sync.aligned.m8n8.x4.shared.b16 {%0,%1,%2,%3},[%4];"
                 : "=r"(r[0]), "=r"(r[1]), "=r"(r[2]), "=r"(r[3]) : "r"(a));
}
__device__ __forceinline__ void ldmB(const unsigned short* t, int n0, int k0, uint32_t r[4]) {
    int lane = threadIdx.x & 31;
    int rr = n0 + (lane & 7) + 8 * (lane >> 4);
    int cc = k0 + 8 * ((lane >> 3) & 1);
    uint32_t a = (uint32_t)__cvta_generic_to_shared(t + rr * STRD + cc);
    asm volatile("ldmatrix.sync.aligned.m8n8.x4.shared.b16 {%0,%1,%2,%3},[%4];"
                 : "=r"(r[0]), "=r"(r[1]), "=r"(r[2]), "=r"(r[3]) : "r"(a));
}
__device__ __forceinline__ void ldmBT(const unsigned short* t, int kk0, int d0, uint32_t r[4]) {
    int lane = threadIdx.x & 31;
    int rr = kk0 + (lane & 7) + 8 * ((lane >> 3) & 1);
    int cc = d0 + 8 * (lane >> 4);
    uint32_t a = (uint32_t)__cvta_generic_to_shared(t + rr * STRD + cc);
    asm volatile("ldmatrix.sync.aligned.m8n8.x4.trans.shared.b16 {%0,%1,%2,%3},[%4];"
                 : "=r"(r[0]), "=r"(r[1]), "=r"(r[2]), "=r"(r[3]) : "r"(a));
}
__device__ __forceinline__ void ldmBT2(const unsigned short* t, int kk0, int d0, uint32_t r[2]) {
    int lane = threadIdx.x & 31;
    int rr = kk0 + (lane & 7) + 8 * ((lane >> 3) & 1);
    uint32_t a = (uint32_t)__cvta_generic_to_shared(t + rr * STRD + d0);
    asm volatile("ldmatrix.sync.aligned.m8n8.x2.trans.shared.b16 {%0,%1},[%2];"
                 : "=r"(r[0]), "=r"(r[1]) : "r"(a));
}
__device__ __forceinline__ void cp16(void* smem_dst, const void* gsrc) {
    uint32_t s = (uint32_t)__cvta_generic_to_shared(smem_dst);
    asm volatile("cp.async.ca.shared.global [%0], [%1], 16;" :: "r"(s), "l"(gsrc));
}

// ---------------------------------------------------------------------------
// Prep: fp32 -> fp16 packed copies of q, hx, Wq, Wk, Wv
// ---------------------------------------------------------------------------
__global__ __launch_bounds__(256) void prep_f16(const float* __restrict__ q,
                                                const float* __restrict__ hx,
                                                const float* __restrict__ Wq,
                                                const float* __restrict__ Wk,
                                                const float* __restrict__ Wv) {
    const int z = blockIdx.y;
    const float* src = (z == 0) ? q : (z == 1) ? hx : (z == 2) ? Wq : (z == 3) ? Wk : Wv;
    uint32_t* dst = (z == 0) ? g_Xq : (z == 1) ? g_Xh : (z == 2) ? g_Wq16 : (z == 3) ? g_Wk16 : g_Wv16;
    size_t n = (z < 2) ? ((size_t)Bb * Ss * Ee / 2) : ((size_t)Hh * Dd * Ee / 2);
    size_t stride = (size_t)gridDim.x * blockDim.x;
    for (size_t i = (size_t)blockIdx.x * blockDim.x + threadIdx.x; i < n; i += stride) {
        float2 v = ((const float2*)src)[i];
        dst[i] = pack_f16x2(v.x, v.y);
    }
}

// mask (int32, nonzero = disallowed) -> bitmask, 64 cols per uint64
__global__ __launch_bounds__(256) void prep_mask(const int* __restrict__ mask) {
    int lane = threadIdx.x & 31;
    size_t gw = ((size_t)blockIdx.x * blockDim.x + threadIdx.x) >> 5;
    size_t nw = ((size_t)gridDim.x * blockDim.x) >> 5;
    const size_t NW = (size_t)Bb * Ss * Ss / 64;
    for (size_t w = gw; w < NW; w += nw) {
        const int* p = mask + w * 64;
        uint32_t b0 = __ballot_sync(0xffffffffu, p[lane] != 0);
        uint32_t b1 = __ballot_sync(0xffffffffu, p[lane + 32] != 0);
        if (lane == 0)
            g_pm64[w] = (unsigned long long)b0 | ((unsigned long long)b1 << 32);
    }
}

// ---------------------------------------------------------------------------
// Projections: C = X @ W^T (fp16 in, fp16 packed out, (B,H,S,D)).
// BM=128, BN=128, BK=64. 128 threads, 4 warps as 2(m64) x 2(n64).
// 2-stage cp.async, SINGLE barrier per chunk: issue -> consume -> wait -> sync.
// 2 CTAs/SM.
// ---------------------------------------------------------------------------
__global__ __launch_bounds__(128, 2) void proj_kernel() {
    extern __shared__ unsigned short sm16[];
    const int z = blockIdx.z;
    const uint32_t* X = (z == 0) ? g_Xq : g_Xh;
    const uint32_t* W = (z == 0) ? g_Wq16 : (z == 1) ? g_Wk16 : g_Wv16;
    uint32_t* dst = (z == 0) ? g_Qh : (z == 1) ? g_Kh : g_Vh;

    const int tid = threadIdx.x;
    const int wid = tid >> 5, lane = tid & 31;
    const int g = lane >> 2, t4 = lane & 3;
    const int wm = wid >> 1, wn = wid & 1;
    const int mbase = blockIdx.y * 128;
    const int nbase = blockIdx.x * 128;

#define PSTAGE(st) (sm16 + (st) * 256 * STRD)
#define PROJ_ISSUE(et, st)                                                        \
    {                                                                             \
        unsigned short* xs_ = PSTAGE(st);                                         \
        unsigned short* ws_ = PSTAGE(st) + 128 * STRD;                            \
        int ew_ = (et) * 32; /* word offset of e-chunk */                         \
        _Pragma("unroll")                                                         \
        for (int i_ = 0; i_ < 16; i_++) {                                         \
            int slot_ = i_ * 128 + tid;                                           \
            if (slot_ < 1024) {                                                   \
                int r_ = slot_ >> 3, c_ = slot_ & 7;                              \
                cp16(xs_ + r_ * STRD + c_ * 8,                                    \
                     X + (size_t)(mbase + r_) * 512 + ew_ + c_ * 4);              \
            } else {                                                              \
                int s2_ = slot_ - 1024;                                           \
                int r_ = s2_ >> 3, c_ = s2_ & 7;                                  \
                cp16(ws_ + r_ * STRD + c_ * 8,                                    \
                     W + (size_t)(nbase + r_) * 512 + ew_ + c_ * 4);              \
            }                                                                     \
        }                                                                         \
        asm volatile("cp.async.commit_group;");                                   \
    }

    float c[4][8][4] = {};
    PROJ_ISSUE(0, 0);
    asm volatile("cp.async.wait_group 0;");
    __syncthreads();                          // stage 0 ready, all warps present

    for (int et = 0; et < 16; et++) {
        // issue next chunk into the other stage: that stage was consumed by all
        // warps in iteration et-1 (proven by the barrier at the end of et-1)
        if (et + 1 < 16) PROJ_ISSUE(et + 1, (et + 1) & 1);

        const unsigned short* Xs = PSTAGE(et & 1);
        const unsigned short* Ws = PSTAGE(et & 1) + 128 * STRD;

#pragma unroll
        for (int ks = 0; ks < 4; ks++) {
            uint32_t ax[4][4], bw[4][4];
#pragma unroll
            for (int mt = 0; mt < 4; mt++) ldmA(Xs, wm * 64 + mt * 16, ks * 16, ax[mt]);
#pragma unroll
            for (int nt2 = 0; nt2 < 4; nt2++) ldmB(Ws, wn * 64 + nt2 * 16, ks * 16, bw[nt2]);
#pragma unroll
            for (int mt = 0; mt < 4; mt++)
#pragma unroll
                for (int nt2 = 0; nt2 < 4; nt2++) {
                    mma16816(c[mt][2 * nt2],     ax[mt], bw[nt2][0], bw[nt2][1]);
                    mma16816(c[mt][2 * nt2 + 1], ax[mt], bw[nt2][2], bw[nt2][3]);
                }
        }

        // single rendezvous: next-stage data arrived AND all warps consumed et
        if (et + 1 < 16) {
            asm volatile("cp.async.wait_group 0;");
            __syncthreads();
        }
    }

    // epilogue: each warp's n64 block == one head
    const int h = blockIdx.x * 2 + wn;
#pragma unroll
    for (int mt = 0; mt < 4; mt++) {
        int m0 = mbase + wm * 64 + mt * 16 + g;
        int b = m0 >> 11, s0 = m0 & 2047;
        size_t base0 = (((size_t)b * Hh + h) * Ss + s0) * (Dd / 2);
        size_t base1 = base0 + 8 * (Dd / 2);
#pragma unroll
        for (int nt = 0; nt < 8; nt++) {
            int dw = nt * 4 + t4;   // d/2
            dst[base0 + dw] = pack_f16x2(c[mt][nt][0], c[mt][nt][1]);
            dst[base1 + dw] = pack_f16x2(c[mt][nt][2], c[mt][nt][3]);
        }
    }
}

// ---------------------------------------------------------------------------
// Flash attention (UNCHANGED from round 9 — proven at 206 us).
// CTA = 128 q-rows x (h, b); 4 warps, warp owns 32 q-rows.
// QK^T in f16 accumulators; mask = hmin2 vs ±inf; exp fused f16x2;
// l via ones-column MMA; 4-stage cp.async, single barrier; rescale-skip vote.
// ---------------------------------------------------------------------------
#define SCLOG2 0.18033688011112042f  // 0.125 * log2(e)
#define MRINIT -30.0f
#define NKT (Ss / 64)                 // 32 k-tiles
#define ASTAGE(st) (sm16 + (st) * 128 * STRD)   // K at +0 (64 rows), V at +64*STRD

__global__ __launch_bounds__(128, 2) void attn_kernel(float* __restrict__ out) {
    extern __shared__ unsigned short sm16[];

    const int qt = blockIdx.x, h = blockIdx.y, b = blockIdx.z;
    const int tid = threadIdx.x;
    const int wid = tid >> 5, lane = tid & 31;
    const int g = lane >> 2, t4 = lane & 3;

    const size_t bh_base = ((size_t)b * Hh + h) * Ss;
    const uint32_t* Kg = g_Kh + bh_base * (Dd / 2);
    const uint32_t* Vg = g_Vh + bh_base * (Dd / 2);

    {
        const uint32_t* Qg = g_Qh + (bh_base + qt * 128) * (Dd / 2);
#pragma unroll
        for (int i = 0; i < 8; i++) {
            int slot = i * 128 + tid;
            int r = slot >> 3, c = slot & 7;
            *(int4*)(sm16 + r * STRD + c * 8) = *(const int4*)&Qg[r * 32 + c * 4];
        }
    }
    __syncthreads();
    uint32_t aq[2][4][4];
#pragma unroll
    for (int mh = 0; mh < 2; mh++)
#pragma unroll
        for (int ks = 0; ks < 4; ks++)
            ldmA(sm16, wid * 32 + mh * 16, ks * 16, aq[mh][ks]);
    __syncthreads();

    {
        const uint32_t one2 = 0x3C003C00u;
        int4 ones4 = make_int4(one2, one2, one2, one2);
#pragma unroll
        for (int k = 0; k < 2; k++) {
            int slot = k * 128 + tid;
            int st = slot >> 6, r = slot & 63;
            *(int4*)(ASTAGE(st) + 64 * STRD + r * STRD + 64) = ones4;
        }
    }

#define ATTN_ISSUE(kt, st)                                                        \
    {                                                                             \
        const uint32_t* ks_ = Kg + (size_t)(kt) * 64 * 32;                        \
        const uint32_t* vs_ = Vg + (size_t)(kt) * 64 * 32;                        \
        unsigned short* kb_ = ASTAGE(st);                                         \
        unsigned short* vb_ = ASTAGE(st) + 64 * STRD;                             \
        _Pragma("unroll")                                                         \
        for (int i_ = 0; i_ < 8; i_++) {                                          \
            int slot_ = i_ * 128 + tid;                                           \
            int r_ = (slot_ >> 3) & 63, c_ = slot_ & 7;                           \
            if (slot_ < 512) cp16(kb_ + r_ * STRD + c_ * 8, ks_ + r_ * 32 + c_ * 4); \
            else             cp16(vb_ + r_ * STRD + c_ * 8, vs_ + r_ * 32 + c_ * 4); \
        }                                                                         \
        asm volatile("cp.async.commit_group;");                                   \
    }

    __syncthreads();
    ATTN_ISSUE(0, 0);
    ATTN_ISSUE(1, 1);
    ATTN_ISSUE(2, 2);

    float o[2][8][4] = {};
    float lacc[2][4] = {};
    float mr[4] = {MRINIT, MRINIT, MRINIT, MRINIT};

    const int r0 = qt * 128 + wid * 32 + g;
    const unsigned long long* pmr = g_pm64 + ((size_t)b * Ss + r0) * (Ss / 64);

    for (int kt = 0; kt < NKT; kt++) {
        unsigned long long mA = pmr[kt];
        unsigned long long mB = pmr[kt + 8 * (Ss / 64)];
        unsigned long long mC = pmr[kt + 16 * (Ss / 64)];
        unsigned long long mD = pmr[kt + 24 * (Ss / 64)];

        asm volatile("cp.async.wait_group 2;");
        __syncthreads();
        if (kt + 3 < NKT) { ATTN_ISSUE(kt + 3, (kt + 3) & 3); }
        else { asm volatile("cp.async.commit_group;"); }

        const unsigned short* Kt = ASTAGE(kt & 3);
        const unsigned short* Vt = ASTAGE(kt & 3) + 64 * STRD;

        uint32_t s2[2][8][2];
#pragma unroll
        for (int mh = 0; mh < 2; mh++)
#pragma unroll
            for (int nt = 0; nt < 8; nt++) { s2[mh][nt][0] = 0u; s2[mh][nt][1] = 0u; }
#pragma unroll
        for (int ks = 0; ks < 4; ks++) {
            uint32_t bk[4][4];
#pragma unroll
            for (int nt2 = 0; nt2 < 4; nt2++) ldmB(Kt, nt2 * 16, ks * 16, bk[nt2]);
#pragma unroll
            for (int mh = 0; mh < 2; mh++)
#pragma unroll
                for (int nt2 = 0; nt2 < 4; nt2++) {
                    mma16816h(s2[mh][2 * nt2],     aq[mh][ks], bk[nt2][0], bk[nt2][1]);
                    mma16816h(s2[mh][2 * nt2 + 1], aq[mh][ks], bk[nt2][2], bk[nt2][3]);
                }
        }

#pragma unroll
        for (int nt = 0; nt < 8; nt++) {
            int sh = nt * 8 + 2 * t4;
            uint32_t a2 = (uint32_t)(mA >> sh) & 3u;
            uint32_t b2 = (uint32_t)(mB >> sh) & 3u;
            uint32_t c2 = (uint32_t)(mC >> sh) & 3u;
            uint32_t d2 = (uint32_t)(mD >> sh) & 3u;
            s2[0][nt][0] = hmin2u(s2[0][nt][0], 0x7C007C00u | ((a2 & 1) << 15) | ((a2 & 2) << 30));
            s2[0][nt][1] = hmin2u(s2[0][nt][1], 0x7C007C00u | ((b2 & 1) << 15) | ((b2 & 2) << 30));
            s2[1][nt][0] = hmin2u(s2[1][nt][0], 0x7C007C00u | ((c2 & 1) << 15) | ((c2 & 2) << 30));
            s2[1][nt][1] = hmin2u(s2[1][nt][1], 0x7C007C00u | ((d2 & 1) << 15) | ((d2 & 2) << 30));
        }

        uint32_t m2[4] = {0xFC00FC00u, 0xFC00FC00u, 0xFC00FC00u, 0xFC00FC00u};
#pragma unroll
        for (int nt = 0; nt < 8; nt++) {
            m2[0] = hmax2u(m2[0], s2[0][nt][0]);
            m2[1] = hmax2u(m2[1], s2[0][nt][1]);
            m2[2] = hmax2u(m2[2], s2[1][nt][0]);
            m2[3] = hmax2u(m2[3], s2[1][nt][1]);
        }
        bool same = true;
        float mn[4];
#pragma unroll
        for (int rgi = 0; rgi < 4; rgi++) {
            float2 f = __half22float2(*(__half2*)&m2[rgi]);
            float mx = fmaxf(f.x, f.y);
            mx = fmaxf(mx, __shfl_xor_sync(0xffffffffu, mx, 1));
            mx = fmaxf(mx, __shfl_xor_sync(0xffffffffu, mx, 2));
            mn[rgi] = fmaxf(mr[rgi], mx);
            same = same && (mn[rgi] == mr[rgi]);
        }
        if (!__all_sync(0xffffffffu, same)) {
            float corr[4];
#pragma unroll
            for (int rgi = 0; rgi < 4; rgi++)
                corr[rgi] = ex2f((mr[rgi] - mn[rgi]) * SCLOG2);
#pragma unroll
            for (int nd = 0; nd < 8; nd++) {
                o[0][nd][0] *= corr[0]; o[0][nd][1] *= corr[0];
                o[0][nd][2] *= corr[1]; o[0][nd][3] *= corr[1];
                o[1][nd][0] *= corr[2]; o[1][nd][1] *= corr[2];
                o[1][nd][2] *= corr[3]; o[1][nd][3] *= corr[3];
            }
            lacc[0][0] *= corr[0]; lacc[0][1] *= corr[0];
            lacc[0][2] *= corr[1]; lacc[0][3] *= corr[1];
            lacc[1][0] *= corr[2]; lacc[1][1] *= corr[2];
            lacc[1][2] *= corr[3]; lacc[1][3] *= corr[3];
        }
#pragma unroll
        for (int rgi = 0; rgi < 4; rgi++) mr[rgi] = mn[rgi];

        const uint32_t sc2 = 0x31C631C6u;
        uint32_t nm2[4];
#pragma unroll
        for (int rgi = 0; rgi < 4; rgi++)
            nm2[rgi] = pack_f16x2(-mr[rgi] * SCLOG2, -mr[rgi] * SCLOG2);
#pragma unroll
        for (int mh = 0; mh < 2; mh++)
#pragma unroll
            for (int nt = 0; nt < 8; nt++) {
                s2[mh][nt][0] = ex2h2(hfma2u(s2[mh][nt][0], sc2, nm2[2 * mh]));
                s2[mh][nt][1] = ex2h2(hfma2u(s2[mh][nt][1], sc2, nm2[2 * mh + 1]));
            }

#pragma unroll
        for (int ks2 = 0; ks2 < 4; ks2++) {
            uint32_t bv[4][4], bl[2];
#pragma unroll
            for (int d2 = 0; d2 < 4; d2++) ldmBT(Vt, ks2 * 16, d2 * 16, bv[d2]);
            ldmBT2(Vt, ks2 * 16, 64, bl);
#pragma unroll
            for (int mh = 0; mh < 2; mh++) {
                const uint32_t pa[4] = {s2[mh][2 * ks2][0], s2[mh][2 * ks2][1],
                                        s2[mh][2 * ks2 + 1][0], s2[mh][2 * ks2 + 1][1]};
#pragma unroll
                for (int d2 = 0; d2 < 4; d2++) {
                    mma16816(o[mh][2 * d2],     pa, bv[d2][0], bv[d2][1]);
                    mma16816(o[mh][2 * d2 + 1], pa, bv[d2][2], bv[d2][3]);
                }
                mma16816(lacc[mh], pa, bl[0], bl[1]);
            }
        }
    }

#pragma unroll
    for (int mh = 0; mh < 2; mh++) {
        float invA = 1.f / fmaxf(lacc[mh][0], 1e-30f);
        float invB = 1.f / fmaxf(lacc[mh][2], 1e-30f);
        int rA = r0 + 16 * mh, rB = rA + 8;
        float* oA = out + ((size_t)b * Ss + rA) * (Hh * Dd) + h * Dd;
        float* oB = out + ((size_t)b * Ss + rB) * (Hh * Dd) + h * Dd;
#pragma unroll
        for (int nd = 0; nd < 8; nd++) {
            int d = nd * 8 + 2 * t4;
            *(float2*)&oA[d] = make_float2(o[mh][nd][0] * invA, o[mh][nd][1] * invA);
            *(float2*)&oB[d] = make_float2(o[mh][nd][2] * invB, o[mh][nd][3] * invB);
        }
    }
}

// ---------------------------------------------------------------------------
extern "C" void kernel_launch(void* const* d_in, const int* in_sizes, int n_in,
                              void* d_out, int out_size) {
    const float* q  = (const float*)d_in[0];
    const float* hx = (const float*)d_in[1];
    const int* mask = (const int*)d_in[2];
    const float* Wq = (const float*)d_in[3];
    const float* Wk = (const float*)d_in[4];
    const float* Wv = (const float*)d_in[5];
    float* out = (float*)d_out;

    prep_f16<<<dim3(4096, 5), 256>>>(q, hx, Wq, Wk, Wv);
    prep_mask<<<2048, 256>>>(mask);

    const int psmem = 2 * 256 * STRD * 2;   // 73728 B (2 stages)
    cudaFuncSetAttribute(proj_kernel, cudaFuncAttributeMaxDynamicSharedMemorySize, psmem);
    proj_kernel<<<dim3(Hh * Dd / 128, Bb * Ss / 128, 3), 128, psmem>>>();

    const int asmem = 4 * 128 * STRD * 2;   // 73728 B
    cudaFuncSetAttribute(attn_kernel, cudaFuncAttributeMaxDynamicSharedMemorySize, asmem);
    attn_kernel<<<dim3(Ss / 128, Hh, Bb), 128, asmem>>>(out);
}